// round 12
// baseline (speedup 1.0000x reference)
#include <cuda_runtime.h>
#include <cuda_bf16.h>
#include <cstdint>

// Problem geometry (fixed)
#define Bb    4
#define Nn    512
#define Hh    12
#define Dh    64
#define HIDD  768
#define Ee    65536
#define NSEG  2048          // Bb*Nn segments
#define NREL  64
#define NCHUNK 256
#define CHUNK  256          // NCHUNK*CHUNK == Ee
#define CAP    512          // max edges per segment handled

#define XN (2048*768)
#define WN (768*768)

// ---------------- device scratch (static; no allocations allowed) ----------------
__device__ float g_K[NSEG * HIDD];
__device__ float g_V[NSEG * HIDD];
__device__ float g_logits[Ee * Hh];          // stored in SEGMENT-SORTED edge order
__device__ unsigned short g_hist[NSEG * NCHUNK];   // [s][c]
__device__ unsigned short g_base[NSEG * NCHUNK];   // [s][c]
__device__ int   g_cnt[NSEG];
__device__ int   g_start[NSEG + 1];
__device__ int   g_spos[Ee];                 // edge -> position in segment order
__device__ int   g_voff[Ee];                 // segment-ordered V row offsets
// relation sort
__device__ unsigned short g_rhist[NREL * NCHUNK];  // [r][c]
__device__ unsigned short g_rbase[NREL * NCHUNK];  // [r][c]
__device__ int   g_rstart[NREL + 1];
__device__ int   g_rsorted[Ee];
// split-bf16 operands
__device__ __nv_bfloat16 g_Xhi[XN];
__device__ __nv_bfloat16 g_Xlo[XN];
__device__ __nv_bfloat16 g_Whi[3 * WN];
__device__ __nv_bfloat16 g_Wlo[3 * WN];
__device__ __nv_bfloat16 g_Qhi[NSEG * HIDD];
__device__ __nv_bfloat16 g_Qlo[NSEG * HIDD];
__device__ __nv_bfloat16 g_Rhi[NREL * 4096];   // transposed: [r][n][k]
__device__ __nv_bfloat16 g_Rlo[NREL * 4096];

// ---------------- helpers ----------------
__device__ __forceinline__ uint32_t smem_u32(const void* p) {
    uint32_t a;
    asm("{ .reg .u64 t; cvta.to.shared.u64 t, %1; cvt.u32.u64 %0, t; }" : "=r"(a) : "l"(p));
    return a;
}
__device__ __forceinline__ void ldmx4(uint32_t* r, uint32_t addr) {
    asm volatile("ldmatrix.sync.aligned.m8n8.x4.shared.b16 {%0,%1,%2,%3}, [%4];"
                 : "=r"(r[0]), "=r"(r[1]), "=r"(r[2]), "=r"(r[3]) : "r"(addr));
}
__device__ __forceinline__ void mma16816(float* c, const uint32_t* a, const uint32_t* b) {
    asm volatile("mma.sync.aligned.m16n8k16.row.col.f32.bf16.bf16.f32 "
                 "{%0,%1,%2,%3}, {%4,%5,%6,%7}, {%8,%9}, {%0,%1,%2,%3};"
                 : "+f"(c[0]), "+f"(c[1]), "+f"(c[2]), "+f"(c[3])
                 : "r"(a[0]), "r"(a[1]), "r"(a[2]), "r"(a[3]), "r"(b[0]), "r"(b[1]));
}
__device__ __forceinline__ void cp16(uint32_t dst, const void* src) {
    asm volatile("cp.async.cg.shared.global [%0], [%1], 16;" :: "r"(dst), "l"(src));
}
#define CPCOMMIT() asm volatile("cp.async.commit_group;" ::: "memory")
#define CPWAIT0()  asm volatile("cp.async.wait_group 0;" ::: "memory")

// ---------------- 0a) split-bf16 conversion (X, W) ----------------
__global__ void kconv(const float* __restrict__ x,
                      const float* __restrict__ wq, const float* __restrict__ wk,
                      const float* __restrict__ wv)
{
    int i = blockIdx.x * 256 + threadIdx.x;
    float v; __nv_bfloat16* hi; __nv_bfloat16* lo; int o;
    if (i < XN) {
        v = x[i]; hi = g_Xhi; lo = g_Xlo; o = i;
    } else {
        int j = i - XN;
        int w = j / WN; o = j - w * WN;
        v = (w == 0 ? wq : (w == 1 ? wk : wv))[o];
        hi = g_Whi + w * WN; lo = g_Wlo + w * WN;
    }
    __nv_bfloat16 h = __float2bfloat16(v);
    hi[o] = h;
    lo[o] = __float2bfloat16(v - __bfloat162float(h));
}

// ---------------- 0b) split-bf16 conversion of R^T (side stream) ----------------
__global__ void kconvR(const float* __restrict__ rel)
{
    int j = blockIdx.x * 256 + threadIdx.x;     // 0..NREL*4096
    int r = j >> 12;
    int rem = j & 4095;
    int kk = rem >> 6;
    int nn = rem & 63;
    float v = rel[j];
    int o = (r << 12) + nn * 64 + kk;           // transposed store
    __nv_bfloat16 h = __float2bfloat16(v);
    g_Rhi[o] = h;
    g_Rlo[o] = __float2bfloat16(v - __bfloat162float(h));
}

// ---------------- 1) QKV projection: mma.sync split-bf16, cp.async 2-stage ----------------
#define ASTR 40                 // padded bf16 row stride
#define QBUF (128 * ASTR * 2)   // bytes per operand buffer (10240)
#define QSTG (4 * QBUF)         // bytes per stage (40960)
#define QKV_SMEM (2 * QSTG)     // 81920
__global__ __launch_bounds__(256, 2) void qkv_hmma(
    const float* __restrict__ bq, const float* __restrict__ bk, const float* __restrict__ bv)
{
    extern __shared__ __align__(16) char qsm[];
    const int t = threadIdx.x;
    const int lane = t & 31;
    const int wid = t >> 5;
    const int wr = wid >> 2;        // 0..1  -> 64-row band
    const int wc = wid & 3;         // 0..3  -> 32-col band
    const int n0 = blockIdx.x * 128;
    const int m0 = blockIdx.y * 128;
    const int z  = blockIdx.z;

    const __nv_bfloat16* Wh = g_Whi + z * WN;
    const __nv_bfloat16* Wl = g_Wlo + z * WN;
    const uint32_t sbase = smem_u32(qsm);

    const int lrow0 = t >> 2;            // iter j: row = lrow0 + 64*j
    const int lf4   = t & 3;

    // preload chunk 0
    {
        #pragma unroll
        for (int j = 0; j < 2; j++) {
            int row = lrow0 + 64 * j;
            long goff = (long)row * HIDD + lf4 * 8;
            uint32_t soff = (uint32_t)(row * ASTR + lf4 * 8) * 2;
            cp16(sbase + 0 * QBUF + soff, g_Xhi + (long)m0 * HIDD + goff);
            cp16(sbase + 1 * QBUF + soff, g_Xlo + (long)m0 * HIDD + goff);
            cp16(sbase + 2 * QBUF + soff, Wh + (long)n0 * HIDD + goff);
            cp16(sbase + 3 * QBUF + soff, Wl + (long)n0 * HIDD + goff);
        }
        CPCOMMIT();
    }

    float acc[4][4][4];
    #pragma unroll
    for (int mi = 0; mi < 4; mi++)
        #pragma unroll
        for (int nj = 0; nj < 4; nj++)
            #pragma unroll
            for (int q = 0; q < 4; q++) acc[mi][nj][q] = 0.f;

    const int g  = lane >> 3;       // octet id 0..3
    const int rr = lane & 7;

    for (int kc = 0; kc < 24; kc++) {
        CPWAIT0();
        __syncthreads();
        if (kc < 23) {
            const int k0 = (kc + 1) * 32;
            const uint32_t stg = sbase + ((kc + 1) & 1) * QSTG;
            #pragma unroll
            for (int j = 0; j < 2; j++) {
                int row = lrow0 + 64 * j;
                long goff = (long)row * HIDD + k0 + lf4 * 8;
                uint32_t soff = (uint32_t)(row * ASTR + lf4 * 8) * 2;
                cp16(stg + 0 * QBUF + soff, g_Xhi + (long)m0 * HIDD + goff);
                cp16(stg + 1 * QBUF + soff, g_Xlo + (long)m0 * HIDD + goff);
                cp16(stg + 2 * QBUF + soff, Wh + (long)n0 * HIDD + goff);
                cp16(stg + 3 * QBUF + soff, Wl + (long)n0 * HIDD + goff);
            }
            CPCOMMIT();
        }

        const uint32_t cs = sbase + (kc & 1) * QSTG;
        const uint32_t sAh_b = cs;
        const uint32_t sAl_b = cs + QBUF;
        const uint32_t sBh_b = cs + 2 * QBUF;
        const uint32_t sBl_b = cs + 3 * QBUF;

        #pragma unroll
        for (int ks = 0; ks < 2; ks++) {
            uint32_t af[4][4], bh[4][2], bl[4][2];
            const int acol = ks * 16 + (g >> 1) * 8;
            #pragma unroll
            for (int mi = 0; mi < 4; mi++) {
                int arow = wr * 64 + mi * 16 + (g & 1) * 8 + rr;
                ldmx4(af[mi], sAh_b + (uint32_t)(arow * ASTR + acol) * 2);
            }
            const int bcol = ks * 16 + (g & 1) * 8;
            #pragma unroll
            for (int np = 0; np < 2; np++) {
                int brow = wc * 32 + np * 16 + (g >> 1) * 8 + rr;
                uint32_t tmp[4];
                ldmx4(tmp, sBh_b + (uint32_t)(brow * ASTR + bcol) * 2);
                bh[2 * np][0] = tmp[0]; bh[2 * np][1] = tmp[1];
                bh[2 * np + 1][0] = tmp[2]; bh[2 * np + 1][1] = tmp[3];
                ldmx4(tmp, sBl_b + (uint32_t)(brow * ASTR + bcol) * 2);
                bl[2 * np][0] = tmp[0]; bl[2 * np][1] = tmp[1];
                bl[2 * np + 1][0] = tmp[2]; bl[2 * np + 1][1] = tmp[3];
            }
            #pragma unroll
            for (int mi = 0; mi < 4; mi++)
                #pragma unroll
                for (int nj = 0; nj < 4; nj++) {
                    mma16816(acc[mi][nj], af[mi], bh[nj]);
                    mma16816(acc[mi][nj], af[mi], bl[nj]);
                }
            #pragma unroll
            for (int mi = 0; mi < 4; mi++) {
                int arow = wr * 64 + mi * 16 + (g & 1) * 8 + rr;
                ldmx4(af[mi], sAl_b + (uint32_t)(arow * ASTR + acol) * 2);
            }
            #pragma unroll
            for (int mi = 0; mi < 4; mi++)
                #pragma unroll
                for (int nj = 0; nj < 4; nj++)
                    mma16816(acc[mi][nj], af[mi], bh[nj]);
        }
    }

    // epilogue
    const float* bias = (z == 0) ? bq : (z == 1) ? bk : bv;
    #pragma unroll
    for (int mi = 0; mi < 4; mi++) {
        int row = m0 + wr * 64 + mi * 16 + (lane >> 2);
        #pragma unroll
        for (int nj = 0; nj < 4; nj++) {
            int col = n0 + wc * 32 + nj * 8 + (lane & 3) * 2;
            float b0 = bias[col], b1 = bias[col + 1];
            float v00 = acc[mi][nj][0] + b0, v01 = acc[mi][nj][1] + b1;
            float v10 = acc[mi][nj][2] + b0, v11 = acc[mi][nj][3] + b1;
            if (z == 0) {
                __nv_bfloat16 h00 = __float2bfloat16(v00), h01 = __float2bfloat16(v01);
                __nv_bfloat16 h10 = __float2bfloat16(v10), h11 = __float2bfloat16(v11);
                __nv_bfloat162 hi0; hi0.x = h00; hi0.y = h01;
                __nv_bfloat162 hi1; hi1.x = h10; hi1.y = h11;
                __nv_bfloat162 lo0; lo0.x = __float2bfloat16(v00 - __bfloat162float(h00));
                                    lo0.y = __float2bfloat16(v01 - __bfloat162float(h01));
                __nv_bfloat162 lo1; lo1.x = __float2bfloat16(v10 - __bfloat162float(h10));
                                    lo1.y = __float2bfloat16(v11 - __bfloat162float(h11));
                *(__nv_bfloat162*)(g_Qhi + (long)row * HIDD + col) = hi0;
                *(__nv_bfloat162*)(g_Qhi + (long)(row + 8) * HIDD + col) = hi1;
                *(__nv_bfloat162*)(g_Qlo + (long)row * HIDD + col) = lo0;
                *(__nv_bfloat162*)(g_Qlo + (long)(row + 8) * HIDD + col) = lo1;
            } else {
                float* outp = (z == 1) ? g_K : g_V;
                *(float2*)(outp + (long)row * HIDD + col) = make_float2(v00, v01);
                *(float2*)(outp + (long)(row + 8) * HIDD + col) = make_float2(v10, v11);
            }
        }
    }
}

// ---------------- 2) deterministic counting sorts (fused, transposed layouts) ----------------
__global__ void khist2(const int* __restrict__ ei)
{
    __shared__ int cnt[NSEG];
    __shared__ int rcnt[NREL];
    const int c = blockIdx.x;
    const int t = threadIdx.x;
    for (int i = t; i < NSEG; i += 256) cnt[i] = 0;
    if (t < NREL) rcnt[t] = 0;
    __syncthreads();
    const int e = c * CHUNK + t;
    const int s = ei[e] * Nn + ei[Ee + e];
    atomicAdd(&cnt[s], 1);
    atomicAdd(&rcnt[ei[3 * Ee + e]], 1);
    __syncthreads();
    for (int i = t; i < NSEG; i += 256) g_hist[i * NCHUNK + c] = (unsigned short)cnt[i];
    if (t < NREL) g_rhist[t * NCHUNK + c] = (unsigned short)rcnt[t];
}

__global__ void kbasewarp2()
{
    const int t = threadIdx.x;
    const int s = blockIdx.x * 8 + (t >> 5);
    const int lane = t & 31;
    uint4 v4 = ((const uint4*)(g_hist + s * NCHUNK))[lane];
    int v[8] = { (int)(v4.x & 0xffff), (int)(v4.x >> 16), (int)(v4.y & 0xffff), (int)(v4.y >> 16),
                 (int)(v4.z & 0xffff), (int)(v4.z >> 16), (int)(v4.w & 0xffff), (int)(v4.w >> 16) };
    int sum = 0;
    #pragma unroll
    for (int i = 0; i < 8; i++) sum += v[i];
    int ex = sum;
    #pragma unroll
    for (int off = 1; off < 32; off <<= 1) {
        int n = __shfl_up_sync(0xffffffffu, ex, off);
        if (lane >= off) ex += n;
    }
    int run = ex - sum;
    unsigned int b[8];
    #pragma unroll
    for (int i = 0; i < 8; i++) { b[i] = (unsigned int)run; run += v[i]; }
    uint4 o;
    o.x = b[0] | (b[1] << 16); o.y = b[2] | (b[3] << 16);
    o.z = b[4] | (b[5] << 16); o.w = b[6] | (b[7] << 16);
    ((uint4*)(g_base + s * NCHUNK))[lane] = o;
    if (lane == 31) g_cnt[s] = run;
}

__global__ void kscan_all()
{
    __shared__ int wsum[32];
    __shared__ int rtot[NREL];
    const int t = threadIdx.x;   // 1024
    const int lane = t & 31, w = t >> 5;
    int a = g_cnt[2 * t], b = g_cnt[2 * t + 1];
    int s = a + b;
    int x = s;
    #pragma unroll
    for (int off = 1; off < 32; off <<= 1) {
        int n = __shfl_up_sync(0xffffffffu, x, off);
        if (lane >= off) x += n;
    }
    if (lane == 31) wsum[w] = x;
    __syncthreads();
    if (w == 0) {
        int y = wsum[lane];
        #pragma unroll
        for (int off = 1; off < 32; off <<= 1) {
            int n = __shfl_up_sync(0xffffffffu, y, off);
            if (lane >= off) y += n;
        }
        wsum[lane] = y;
    }
    __syncthreads();
    int base = (w ? wsum[w - 1] : 0) + x - s;
    g_start[2 * t + 1] = base + a;
    g_start[2 * t + 2] = base + a + b;
    if (t == 0) g_start[0] = 0;
    #pragma unroll
    for (int q = 0; q < 2; q++) {
        int r = w * 2 + q;
        uint4 v4 = ((const uint4*)(g_rhist + r * NCHUNK))[lane];
        int v[8] = { (int)(v4.x & 0xffff), (int)(v4.x >> 16), (int)(v4.y & 0xffff), (int)(v4.y >> 16),
                     (int)(v4.z & 0xffff), (int)(v4.z >> 16), (int)(v4.w & 0xffff), (int)(v4.w >> 16) };
        int sm2 = 0;
        #pragma unroll
        for (int i = 0; i < 8; i++) sm2 += v[i];
        int ex = sm2;
        #pragma unroll
        for (int off = 1; off < 32; off <<= 1) {
            int n = __shfl_up_sync(0xffffffffu, ex, off);
            if (lane >= off) ex += n;
        }
        int run = ex - sm2;
        unsigned int bb[8];
        #pragma unroll
        for (int i = 0; i < 8; i++) { bb[i] = (unsigned int)run; run += v[i]; }
        uint4 o;
        o.x = bb[0] | (bb[1] << 16); o.y = bb[2] | (bb[3] << 16);
        o.z = bb[4] | (bb[5] << 16); o.w = bb[6] | (bb[7] << 16);
        ((uint4*)(g_rbase + r * NCHUNK))[lane] = o;
        if (lane == 31) rtot[r] = run;
    }
    __syncthreads();
    if (t < 32) {
        int a2 = rtot[2 * t], b2 = rtot[2 * t + 1];
        int s2 = a2 + b2;
        int x2 = s2;
        #pragma unroll
        for (int off = 1; off < 32; off <<= 1) {
            int n = __shfl_up_sync(0xffffffffu, x2, off);
            if (t >= off) x2 += n;
        }
        int rb = x2 - s2;
        g_rstart[2 * t + 1] = rb + a2;
        g_rstart[2 * t + 2] = rb + s2;
        if (t == 0) g_rstart[0] = 0;
    }
}

__global__ void kscatter2(const int* __restrict__ ei)
{
    __shared__ int segs[CHUNK];
    __shared__ int rels[CHUNK];
    const int c = blockIdx.x;
    const int t = threadIdx.x;
    const int e = c * CHUNK + t;
    const int b = ei[e], hn = ei[Ee + e], tn = ei[2 * Ee + e], r = ei[3 * Ee + e];
    const int s = b * Nn + hn;
    segs[t] = s;
    rels[t] = r;
    __syncthreads();
    int rank = 0, rrank = 0;
    for (int i = 0; i < t; i++) {
        rank  += (segs[i] == s);
        rrank += (rels[i] == r);
    }
    int pos = g_start[s] + (int)g_base[s * NCHUNK + c] + rank;
    g_spos[e] = pos;
    g_voff[pos] = (b * Nn + tn) * HIDD;
    g_rsorted[g_rstart[r] + (int)g_rbase[r * NCHUNK + c] + rrank] = e;
}

// ---------------- 3) relation-batched logits on tensor cores ----------------
// K rows prefetched to REGISTERS (no smem stage) — consumed only in the epilogue dot.
#define RSTR 72   // bf16 elem stride (144B rows -> conflict-free ldmatrix)
#define EDGE_SMEM (18432 + 18432 + 9216 + 9216 + 192)
__global__ __launch_bounds__(256, 2) void kedge2(const int* __restrict__ ei)
{
    extern __shared__ __align__(16) char sm[];
    __nv_bfloat16* sAh = (__nv_bfloat16*)(sm);
    __nv_bfloat16* sAl = (__nv_bfloat16*)(sm + 18432);
    __nv_bfloat16* sRh = (__nv_bfloat16*)(sm + 36864);
    __nv_bfloat16* sRl = (__nv_bfloat16*)(sm + 46080);
    int* qoff = (int*)(sm + 55296);
    int* koff = qoff + 12;
    int* spv  = koff + 12;

    const int r  = blockIdx.x;
    const int t  = threadIdx.x;
    const int rs = g_rstart[r];
    const int total = (g_rstart[r + 1] - rs) * Hh;
    const int j0 = blockIdx.y * 128;
    if (j0 >= total) return;

    const uint32_t sAh_b = smem_u32(sAh), sAl_b = smem_u32(sAl);
    const uint32_t sRh_b = smem_u32(sRh), sRl_b = smem_u32(sRl);

    // R tile loads (independent of edge offsets) — issue first
    {
        const __nv_bfloat16* Rh = g_Rhi + (r << 12);
        const __nv_bfloat16* Rl = g_Rlo + (r << 12);
        #pragma unroll
        for (int i = t; i < 512; i += 256) {
            int n = i >> 3, f = i & 7;
            uint32_t soff = (uint32_t)(n * RSTR + f * 8) * 2;
            cp16(sRh_b + soff, Rh + n * 64 + f * 8);
            cp16(sRl_b + soff, Rl + n * 64 + f * 8);
        }
        CPCOMMIT();
    }

    const int e_first = j0 / Hh;
    const int jlast = min(j0 + 127, total - 1);
    const int nloc = jlast / Hh - e_first + 1;       // <= 12

    if (t < nloc) {
        int e = g_rsorted[rs + e_first + t];
        int b = ei[e], hn = ei[Ee + e], tn = ei[2 * Ee + e];
        qoff[t] = (b * Nn + hn) * HIDD;
        koff[t] = (b * Nn + tn) * HIDD;
        spv[t]  = g_spos[e];
    }
    __syncthreads();

    // gather A (hi/lo) rows via cp.async
    #pragma unroll
    for (int i = t; i < 1024; i += 256) {
        int row = i >> 3, f = i & 7;
        int j = j0 + row; if (j > total - 1) j = total - 1;
        int le = j / Hh - e_first;
        int h = j % Hh;
        int off = qoff[le] + h * 64 + f * 8;
        uint32_t soff = (uint32_t)(row * RSTR + f * 8) * 2;
        cp16(sAh_b + soff, g_Qhi + off);
        cp16(sAl_b + soff, g_Qlo + off);
    }
    CPCOMMIT();

    // K prefetch into REGISTERS (issued now, consumed after the MMA loop)
    const int lane = t & 31;
    const int wm = t >> 5;          // warp -> rows wm*16..+15
    const int rlo = wm * 16 + (lane >> 2);
    const int rhi = rlo + 8;
    float2 kvlo[8], kvhi[8];
    {
        int jlo = j0 + rlo; if (jlo > total - 1) jlo = total - 1;
        int jhi = j0 + rhi; if (jhi > total - 1) jhi = total - 1;
        const float* kplo = g_K + koff[jlo / Hh - e_first] + (jlo % Hh) * 64 + (lane & 3) * 2;
        const float* kphi = g_K + koff[jhi / Hh - e_first] + (jhi % Hh) * 64 + (lane & 3) * 2;
        #pragma unroll
        for (int nt = 0; nt < 8; nt++) {
            kvlo[nt] = *(const float2*)(kplo + nt * 8);
            kvhi[nt] = *(const float2*)(kphi + nt * 8);
        }
    }

    CPWAIT0();
    __syncthreads();

    const int g = lane >> 3, rr = lane & 7;

    float acc[8][4];
    #pragma unroll
    for (int nt = 0; nt < 8; nt++)
        #pragma unroll
        for (int q = 0; q < 4; q++) acc[nt][q] = 0.f;

    #pragma unroll
    for (int ks = 0; ks < 4; ks++) {
        uint32_t bh[8][2], bl[8][2], af[4];
        const int bcol = ks * 16 + (g & 1) * 8;
        #pragma unroll
        for (int np = 0; np < 4; np++) {
            int brow = np * 16 + (g >> 1) * 8 + rr;
            uint32_t tmp[4];
            ldmx4(tmp, sRh_b + (uint32_t)(brow * RSTR + bcol) * 2);
            bh[2 * np][0] = tmp[0]; bh[2 * np][1] = tmp[1];
            bh[2 * np + 1][0] = tmp[2]; bh[2 * np + 1][1] = tmp[3];
            ldmx4(tmp, sRl_b + (uint32_t)(brow * RSTR + bcol) * 2);
            bl[2 * np][0] = tmp[0]; bl[2 * np][1] = tmp[1];
            bl[2 * np + 1][0] = tmp[2]; bl[2 * np + 1][1] = tmp[3];
        }
        const int acol = ks * 16 + (g >> 1) * 8;
        const int arow = wm * 16 + (g & 1) * 8 + rr;
        ldmx4(af, sAh_b + (uint32_t)(arow * RSTR + acol) * 2);
        #pragma unroll
        for (int nt = 0; nt < 8; nt++) {
            mma16816(acc[nt], af, bh[nt]);
            mma16816(acc[nt], af, bl[nt]);
        }
        ldmx4(af, sAl_b + (uint32_t)(arow * RSTR + acol) * 2);
        #pragma unroll
        for (int nt = 0; nt < 8; nt++)
            mma16816(acc[nt], af, bh[nt]);
    }

    // epilogue: dot Qp rows with register-held K values (fp32)
    float slo = 0.f, shi = 0.f;
    #pragma unroll
    for (int nt = 0; nt < 8; nt++) {
        slo += acc[nt][0] * kvlo[nt].x + acc[nt][1] * kvlo[nt].y;
        shi += acc[nt][2] * kvhi[nt].x + acc[nt][3] * kvhi[nt].y;
    }
    slo += __shfl_xor_sync(0xffffffffu, slo, 1);
    slo += __shfl_xor_sync(0xffffffffu, slo, 2);
    shi += __shfl_xor_sync(0xffffffffu, shi, 1);
    shi += __shfl_xor_sync(0xffffffffu, shi, 2);
    if ((lane & 3) == 0) {
        int j = j0 + rlo;
        if (j < total) {
            int le = j / Hh - e_first;
            g_logits[spv[le] * Hh + (j % Hh)] = slo * 0.125f;
        }
        j = j0 + rhi;
        if (j < total) {
            int le = j / Hh - e_first;
            g_logits[spv[le] * Hh + (j % Hh)] = shi * 0.125f;
        }
    }
}

// ---------------- 4) per-segment softmax + V aggregation (coalesced inputs) ----------------
__global__ __launch_bounds__(128) void kagg(float* __restrict__ out)
{
    __shared__ float    exb[CAP * Hh];   // 24 KB
    __shared__ int      voff[CAP];       // 2 KB
    __shared__ unsigned umax[Hh];
    __shared__ float    mx[Hh], dnm[Hh];

    const int s = blockIdx.x;
    const int t = threadIdx.x;
    const int beg = g_start[s];
    int cnt = g_start[s + 1] - beg;
    if (cnt > CAP) cnt = CAP;
    float* orow = out + s * HIDD;

    if (cnt == 0) {
        #pragma unroll
        for (int j = 0; j < 6; j++) orow[t + 128 * j] = 0.f;
        return;
    }

    if (t < Hh) umax[t] = 0u;
    __syncthreads();

    for (int i = t; i < cnt; i += 128) voff[i] = g_voff[beg + i];
    const float* lsrc = g_logits + (long)beg * Hh;
    for (int j = t; j < cnt * Hh; j += 128) {
        float l = lsrc[j];
        exb[j] = l;
        int h = j % Hh;
        unsigned bits = __float_as_uint(l);
        unsigned key  = (bits & 0x80000000u) ? ~bits : (bits | 0x80000000u);
        atomicMax(&umax[h], key);   // order-independent -> deterministic
    }
    __syncthreads();

    if (t < Hh) {
        unsigned key  = umax[t];
        unsigned bits = (key & 0x80000000u) ? (key & 0x7fffffffu) : ~key;
        mx[t] = __uint_as_float(bits);
    }
    __syncthreads();

    for (int j = t; j < cnt * Hh; j += 128) {
        int h = j % Hh;
        exb[j] = __expf(exb[j] - mx[h]);
    }
    __syncthreads();

    const int w = t >> 5, lane = t & 31;
    #pragma unroll
    for (int jj = 0; jj < 3; jj++) {
        int h = w * 3 + jj;
        float p = 0.f;
        for (int i = lane; i < cnt; i += 32) p += exb[i * Hh + h];
        #pragma unroll
        for (int off = 16; off; off >>= 1) p += __shfl_xor_sync(0xffffffffu, p, off);
        if (lane == 0) dnm[h] = p;
    }
    __syncthreads();

    float rd[6], accr[6];
    int hcol[6];
    #pragma unroll
    for (int j = 0; j < 6; j++) {
        int c = t + 128 * j;
        hcol[j] = c >> 6;
        rd[j] = 1.f / dnm[hcol[j]];
        accr[j] = 0.f;
    }
    #pragma unroll 2
    for (int i = 0; i < cnt; i++) {
        const float* vrow = g_V + voff[i];
        const float* exr  = &exb[i * Hh];
        #pragma unroll
        for (int j = 0; j < 6; j++) {
            float p = exr[hcol[j]] * rd[j];
            accr[j] += p * vrow[t + 128 * j];
        }
    }
    #pragma unroll
    for (int j = 0; j < 6; j++) orow[t + 128 * j] = accr[j];
}

// ---------------- launch ----------------
extern "C" void kernel_launch(void* const* d_in, const int* in_sizes, int n_in,
                              void* d_out, int out_size)
{
    const float* node_states = (const float*)d_in[0];
    const int*   edge_idx    = (const int*)  d_in[1];
    // d_in[2] = node_type_ids (unused)
    const float* Wq = (const float*)d_in[3];
    const float* bq = (const float*)d_in[4];
    const float* Wk = (const float*)d_in[5];
    const float* bk = (const float*)d_in[6];
    const float* Wv = (const float*)d_in[7];
    const float* bv = (const float*)d_in[8];
    const float* rel = (const float*)d_in[9];
    float* out = (float*)d_out;

    static cudaStream_t s1 = nullptr;
    static cudaEvent_t evRoot = nullptr, evSort = nullptr;
    static bool init_done = false;
    if (!init_done) {
        cudaFuncSetAttribute(kedge2, cudaFuncAttributeMaxDynamicSharedMemorySize, EDGE_SMEM);
        cudaFuncSetAttribute(qkv_hmma, cudaFuncAttributeMaxDynamicSharedMemorySize, QKV_SMEM);
        cudaStreamCreateWithFlags(&s1, cudaStreamNonBlocking);
        cudaEventCreateWithFlags(&evRoot, cudaEventDisableTiming);
        cudaEventCreateWithFlags(&evSort, cudaEventDisableTiming);
        init_done = true;
    }

    // ---- fork: R-conv + sort chain on s1; X/W-conv + full QKV on main ----
    cudaEventRecord(evRoot, 0);
    cudaStreamWaitEvent(s1, evRoot, 0);

    // s1: R^T conversion (only needed by kedge2) + deterministic counting sorts
    kconvR<<<(NREL * 4096) / 256, 256, 0, s1>>>(rel);
    khist2<<<NCHUNK, 256, 0, s1>>>(edge_idx);
    kbasewarp2<<<NSEG / 8, 256, 0, s1>>>();
    kscan_all<<<1, 1024, 0, s1>>>();
    kscatter2<<<NCHUNK, CHUNK, 0, s1>>>(edge_idx);
    cudaEventRecord(evSort, s1);

    // main: split-bf16 conversion of X, W
    kconv<<<(XN + 3 * WN) / 256, 256>>>(node_states, Wq, Wk, Wv);

    // main: Q,K,V projections (288 blocks -> one full concurrent wave)
    qkv_hmma<<<dim3(6, 16, 3), 256, QKV_SMEM>>>(bq, bk, bv);

    // join sort(+R conv), then relation-batched logits
    cudaStreamWaitEvent(0, evSort, 0);
    kedge2<<<dim3(NREL, 120), 256, EDGE_SMEM>>>(edge_idx);

    // per-segment softmax + aggregation
    kagg<<<NSEG, 128>>>(out);
}

// round 13
// speedup vs baseline: 1.0402x; 1.0402x over previous
#include <cuda_runtime.h>
#include <cuda_bf16.h>
#include <cstdint>

// Problem geometry (fixed)
#define Bb    4
#define Nn    512
#define Hh    12
#define Dh    64
#define HIDD  768
#define Ee    65536
#define NSEG  2048          // Bb*Nn segments
#define NREL  64
#define NCHUNK 256
#define CHUNK  256          // NCHUNK*CHUNK == Ee
#define CAP    512          // max edges per segment handled

#define XN (2048*768)
#define WN (768*768)

// ---------------- device scratch (static; no allocations allowed) ----------------
__device__ float g_K[NSEG * HIDD];
__device__ float g_V[NSEG * HIDD];
__device__ float g_logits[Ee * Hh];          // stored in SEGMENT-SORTED edge order
__device__ unsigned short g_hist[NSEG * NCHUNK];   // [s][c]
__device__ unsigned short g_base[NSEG * NCHUNK];   // [s][c]
__device__ int   g_cnt[NSEG];
__device__ int   g_start[NSEG + 1];
__device__ int   g_spos[Ee];                 // edge -> position in segment order
__device__ int   g_voff[Ee];                 // segment-ordered V row offsets
// relation sort
__device__ unsigned short g_rhist[NREL * NCHUNK];  // [r][c]
__device__ unsigned short g_rbase[NREL * NCHUNK];  // [r][c]
__device__ int   g_rstart[NREL + 1];
__device__ int   g_rsorted[Ee];
// split-bf16 operands
__device__ __nv_bfloat16 g_Xhi[XN];
__device__ __nv_bfloat16 g_Xlo[XN];
__device__ __nv_bfloat16 g_Whi[3 * WN];
__device__ __nv_bfloat16 g_Wlo[3 * WN];
__device__ __nv_bfloat16 g_Qhi[NSEG * HIDD];
__device__ __nv_bfloat16 g_Qlo[NSEG * HIDD];
__device__ __nv_bfloat16 g_Rhi[NREL * 4096];   // transposed: [r][n][k]
__device__ __nv_bfloat16 g_Rlo[NREL * 4096];

// ---------------- helpers ----------------
__device__ __forceinline__ uint32_t smem_u32(const void* p) {
    uint32_t a;
    asm("{ .reg .u64 t; cvta.to.shared.u64 t, %1; cvt.u32.u64 %0, t; }" : "=r"(a) : "l"(p));
    return a;
}
__device__ __forceinline__ void ldmx4(uint32_t* r, uint32_t addr) {
    asm volatile("ldmatrix.sync.aligned.m8n8.x4.shared.b16 {%0,%1,%2,%3}, [%4];"
                 : "=r"(r[0]), "=r"(r[1]), "=r"(r[2]), "=r"(r[3]) : "r"(addr));
}
__device__ __forceinline__ void mma16816(float* c, const uint32_t* a, const uint32_t* b) {
    asm volatile("mma.sync.aligned.m16n8k16.row.col.f32.bf16.bf16.f32 "
                 "{%0,%1,%2,%3}, {%4,%5,%6,%7}, {%8,%9}, {%0,%1,%2,%3};"
                 : "+f"(c[0]), "+f"(c[1]), "+f"(c[2]), "+f"(c[3])
                 : "r"(a[0]), "r"(a[1]), "r"(a[2]), "r"(a[3]), "r"(b[0]), "r"(b[1]));
}
__device__ __forceinline__ void cp16(uint32_t dst, const void* src) {
    asm volatile("cp.async.cg.shared.global [%0], [%1], 16;" :: "r"(dst), "l"(src));
}
#define CPCOMMIT() asm volatile("cp.async.commit_group;" ::: "memory")
#define CPWAIT0()  asm volatile("cp.async.wait_group 0;" ::: "memory")
#define CPWAIT1()  asm volatile("cp.async.wait_group 1;" ::: "memory")

// ---------------- 0a) split-bf16 conversion (X, W) ----------------
__global__ void kconv(const float* __restrict__ x,
                      const float* __restrict__ wq, const float* __restrict__ wk,
                      const float* __restrict__ wv)
{
    int i = blockIdx.x * 256 + threadIdx.x;
    float v; __nv_bfloat16* hi; __nv_bfloat16* lo; int o;
    if (i < XN) {
        v = x[i]; hi = g_Xhi; lo = g_Xlo; o = i;
    } else {
        int j = i - XN;
        int w = j / WN; o = j - w * WN;
        v = (w == 0 ? wq : (w == 1 ? wk : wv))[o];
        hi = g_Whi + w * WN; lo = g_Wlo + w * WN;
    }
    __nv_bfloat16 h = __float2bfloat16(v);
    hi[o] = h;
    lo[o] = __float2bfloat16(v - __bfloat162float(h));
}

// ---------------- 0b) split-bf16 conversion of R^T (side stream) ----------------
__global__ void kconvR(const float* __restrict__ rel)
{
    int j = blockIdx.x * 256 + threadIdx.x;     // 0..NREL*4096
    int r = j >> 12;
    int rem = j & 4095;
    int kk = rem >> 6;
    int nn = rem & 63;
    float v = rel[j];
    int o = (r << 12) + nn * 64 + kk;           // transposed store
    __nv_bfloat16 h = __float2bfloat16(v);
    g_Rhi[o] = h;
    g_Rlo[o] = __float2bfloat16(v - __bfloat162float(h));
}

// ---------------- 1) QKV projection: mma.sync split-bf16, cp.async 2-stage ----------------
#define ASTR 40                 // padded bf16 row stride
#define QBUF (128 * ASTR * 2)   // bytes per operand buffer (10240)
#define QSTG (4 * QBUF)         // bytes per stage (40960)
#define QKV_SMEM (2 * QSTG)     // 81920
__global__ __launch_bounds__(256, 2) void qkv_hmma(
    const float* __restrict__ bq, const float* __restrict__ bk, const float* __restrict__ bv)
{
    extern __shared__ __align__(16) char qsm[];
    const int t = threadIdx.x;
    const int lane = t & 31;
    const int wid = t >> 5;
    const int wr = wid >> 2;        // 0..1  -> 64-row band
    const int wc = wid & 3;         // 0..3  -> 32-col band
    const int n0 = blockIdx.x * 128;
    const int m0 = blockIdx.y * 128;
    const int z  = blockIdx.z;

    const __nv_bfloat16* Wh = g_Whi + z * WN;
    const __nv_bfloat16* Wl = g_Wlo + z * WN;
    const uint32_t sbase = smem_u32(qsm);

    const int lrow0 = t >> 2;            // iter j: row = lrow0 + 64*j
    const int lf4   = t & 3;

    // preload chunk 0
    {
        #pragma unroll
        for (int j = 0; j < 2; j++) {
            int row = lrow0 + 64 * j;
            long goff = (long)row * HIDD + lf4 * 8;
            uint32_t soff = (uint32_t)(row * ASTR + lf4 * 8) * 2;
            cp16(sbase + 0 * QBUF + soff, g_Xhi + (long)m0 * HIDD + goff);
            cp16(sbase + 1 * QBUF + soff, g_Xlo + (long)m0 * HIDD + goff);
            cp16(sbase + 2 * QBUF + soff, Wh + (long)n0 * HIDD + goff);
            cp16(sbase + 3 * QBUF + soff, Wl + (long)n0 * HIDD + goff);
        }
        CPCOMMIT();
    }

    float acc[4][4][4];
    #pragma unroll
    for (int mi = 0; mi < 4; mi++)
        #pragma unroll
        for (int nj = 0; nj < 4; nj++)
            #pragma unroll
            for (int q = 0; q < 4; q++) acc[mi][nj][q] = 0.f;

    const int g  = lane >> 3;       // octet id 0..3
    const int rr = lane & 7;

    for (int kc = 0; kc < 24; kc++) {
        CPWAIT0();
        __syncthreads();
        if (kc < 23) {
            const int k0 = (kc + 1) * 32;
            const uint32_t stg = sbase + ((kc + 1) & 1) * QSTG;
            #pragma unroll
            for (int j = 0; j < 2; j++) {
                int row = lrow0 + 64 * j;
                long goff = (long)row * HIDD + k0 + lf4 * 8;
                uint32_t soff = (uint32_t)(row * ASTR + lf4 * 8) * 2;
                cp16(stg + 0 * QBUF + soff, g_Xhi + (long)m0 * HIDD + goff);
                cp16(stg + 1 * QBUF + soff, g_Xlo + (long)m0 * HIDD + goff);
                cp16(stg + 2 * QBUF + soff, Wh + (long)n0 * HIDD + goff);
                cp16(stg + 3 * QBUF + soff, Wl + (long)n0 * HIDD + goff);
            }
            CPCOMMIT();
        }

        const uint32_t cs = sbase + (kc & 1) * QSTG;
        const uint32_t sAh_b = cs;
        const uint32_t sAl_b = cs + QBUF;
        const uint32_t sBh_b = cs + 2 * QBUF;
        const uint32_t sBl_b = cs + 3 * QBUF;

        #pragma unroll
        for (int ks = 0; ks < 2; ks++) {
            uint32_t af[4][4], bh[4][2], bl[4][2];
            const int acol = ks * 16 + (g >> 1) * 8;
            #pragma unroll
            for (int mi = 0; mi < 4; mi++) {
                int arow = wr * 64 + mi * 16 + (g & 1) * 8 + rr;
                ldmx4(af[mi], sAh_b + (uint32_t)(arow * ASTR + acol) * 2);
            }
            const int bcol = ks * 16 + (g & 1) * 8;
            #pragma unroll
            for (int np = 0; np < 2; np++) {
                int brow = wc * 32 + np * 16 + (g >> 1) * 8 + rr;
                uint32_t tmp[4];
                ldmx4(tmp, sBh_b + (uint32_t)(brow * ASTR + bcol) * 2);
                bh[2 * np][0] = tmp[0]; bh[2 * np][1] = tmp[1];
                bh[2 * np + 1][0] = tmp[2]; bh[2 * np + 1][1] = tmp[3];
                ldmx4(tmp, sBl_b + (uint32_t)(brow * ASTR + bcol) * 2);
                bl[2 * np][0] = tmp[0]; bl[2 * np][1] = tmp[1];
                bl[2 * np + 1][0] = tmp[2]; bl[2 * np + 1][1] = tmp[3];
            }
            #pragma unroll
            for (int mi = 0; mi < 4; mi++)
                #pragma unroll
                for (int nj = 0; nj < 4; nj++) {
                    mma16816(acc[mi][nj], af[mi], bh[nj]);
                    mma16816(acc[mi][nj], af[mi], bl[nj]);
                }
            #pragma unroll
            for (int mi = 0; mi < 4; mi++) {
                int arow = wr * 64 + mi * 16 + (g & 1) * 8 + rr;
                ldmx4(af[mi], sAl_b + (uint32_t)(arow * ASTR + acol) * 2);
            }
            #pragma unroll
            for (int mi = 0; mi < 4; mi++)
                #pragma unroll
                for (int nj = 0; nj < 4; nj++)
                    mma16816(acc[mi][nj], af[mi], bh[nj]);
        }
    }

    // epilogue
    const float* bias = (z == 0) ? bq : (z == 1) ? bk : bv;
    #pragma unroll
    for (int mi = 0; mi < 4; mi++) {
        int row = m0 + wr * 64 + mi * 16 + (lane >> 2);
        #pragma unroll
        for (int nj = 0; nj < 4; nj++) {
            int col = n0 + wc * 32 + nj * 8 + (lane & 3) * 2;
            float b0 = bias[col], b1 = bias[col + 1];
            float v00 = acc[mi][nj][0] + b0, v01 = acc[mi][nj][1] + b1;
            float v10 = acc[mi][nj][2] + b0, v11 = acc[mi][nj][3] + b1;
            if (z == 0) {
                __nv_bfloat16 h00 = __float2bfloat16(v00), h01 = __float2bfloat16(v01);
                __nv_bfloat16 h10 = __float2bfloat16(v10), h11 = __float2bfloat16(v11);
                __nv_bfloat162 hi0; hi0.x = h00; hi0.y = h01;
                __nv_bfloat162 hi1; hi1.x = h10; hi1.y = h11;
                __nv_bfloat162 lo0; lo0.x = __float2bfloat16(v00 - __bfloat162float(h00));
                                    lo0.y = __float2bfloat16(v01 - __bfloat162float(h01));
                __nv_bfloat162 lo1; lo1.x = __float2bfloat16(v10 - __bfloat162float(h10));
                                    lo1.y = __float2bfloat16(v11 - __bfloat162float(h11));
                *(__nv_bfloat162*)(g_Qhi + (long)row * HIDD + col) = hi0;
                *(__nv_bfloat162*)(g_Qhi + (long)(row + 8) * HIDD + col) = hi1;
                *(__nv_bfloat162*)(g_Qlo + (long)row * HIDD + col) = lo0;
                *(__nv_bfloat162*)(g_Qlo + (long)(row + 8) * HIDD + col) = lo1;
            } else {
                float* outp = (z == 1) ? g_K : g_V;
                *(float2*)(outp + (long)row * HIDD + col) = make_float2(v00, v01);
                *(float2*)(outp + (long)(row + 8) * HIDD + col) = make_float2(v10, v11);
            }
        }
    }
}

// ---------------- 2) deterministic counting sorts (fused, transposed layouts) ----------------
__global__ void khist2(const int* __restrict__ ei)
{
    __shared__ int cnt[NSEG];
    __shared__ int rcnt[NREL];
    const int c = blockIdx.x;
    const int t = threadIdx.x;
    for (int i = t; i < NSEG; i += 256) cnt[i] = 0;
    if (t < NREL) rcnt[t] = 0;
    __syncthreads();
    const int e = c * CHUNK + t;
    const int s = ei[e] * Nn + ei[Ee + e];
    atomicAdd(&cnt[s], 1);
    atomicAdd(&rcnt[ei[3 * Ee + e]], 1);
    __syncthreads();
    for (int i = t; i < NSEG; i += 256) g_hist[i * NCHUNK + c] = (unsigned short)cnt[i];
    if (t < NREL) g_rhist[t * NCHUNK + c] = (unsigned short)rcnt[t];
}

__global__ void kbasewarp2()
{
    const int t = threadIdx.x;
    const int s = blockIdx.x * 8 + (t >> 5);
    const int lane = t & 31;
    uint4 v4 = ((const uint4*)(g_hist + s * NCHUNK))[lane];
    int v[8] = { (int)(v4.x & 0xffff), (int)(v4.x >> 16), (int)(v4.y & 0xffff), (int)(v4.y >> 16),
                 (int)(v4.z & 0xffff), (int)(v4.z >> 16), (int)(v4.w & 0xffff), (int)(v4.w >> 16) };
    int sum = 0;
    #pragma unroll
    for (int i = 0; i < 8; i++) sum += v[i];
    int ex = sum;
    #pragma unroll
    for (int off = 1; off < 32; off <<= 1) {
        int n = __shfl_up_sync(0xffffffffu, ex, off);
        if (lane >= off) ex += n;
    }
    int run = ex - sum;
    unsigned int b[8];
    #pragma unroll
    for (int i = 0; i < 8; i++) { b[i] = (unsigned int)run; run += v[i]; }
    uint4 o;
    o.x = b[0] | (b[1] << 16); o.y = b[2] | (b[3] << 16);
    o.z = b[4] | (b[5] << 16); o.w = b[6] | (b[7] << 16);
    ((uint4*)(g_base + s * NCHUNK))[lane] = o;
    if (lane == 31) g_cnt[s] = run;
}

__global__ void kscan_all()
{
    __shared__ int wsum[32];
    __shared__ int rtot[NREL];
    const int t = threadIdx.x;   // 1024
    const int lane = t & 31, w = t >> 5;
    int a = g_cnt[2 * t], b = g_cnt[2 * t + 1];
    int s = a + b;
    int x = s;
    #pragma unroll
    for (int off = 1; off < 32; off <<= 1) {
        int n = __shfl_up_sync(0xffffffffu, x, off);
        if (lane >= off) x += n;
    }
    if (lane == 31) wsum[w] = x;
    __syncthreads();
    if (w == 0) {
        int y = wsum[lane];
        #pragma unroll
        for (int off = 1; off < 32; off <<= 1) {
            int n = __shfl_up_sync(0xffffffffu, y, off);
            if (lane >= off) y += n;
        }
        wsum[lane] = y;
    }
    __syncthreads();
    int base = (w ? wsum[w - 1] : 0) + x - s;
    g_start[2 * t + 1] = base + a;
    g_start[2 * t + 2] = base + a + b;
    if (t == 0) g_start[0] = 0;
    #pragma unroll
    for (int q = 0; q < 2; q++) {
        int r = w * 2 + q;
        uint4 v4 = ((const uint4*)(g_rhist + r * NCHUNK))[lane];
        int v[8] = { (int)(v4.x & 0xffff), (int)(v4.x >> 16), (int)(v4.y & 0xffff), (int)(v4.y >> 16),
                     (int)(v4.z & 0xffff), (int)(v4.z >> 16), (int)(v4.w & 0xffff), (int)(v4.w >> 16) };
        int sm2 = 0;
        #pragma unroll
        for (int i = 0; i < 8; i++) sm2 += v[i];
        int ex = sm2;
        #pragma unroll
        for (int off = 1; off < 32; off <<= 1) {
            int n = __shfl_up_sync(0xffffffffu, ex, off);
            if (lane >= off) ex += n;
        }
        int run = ex - sm2;
        unsigned int bb[8];
        #pragma unroll
        for (int i = 0; i < 8; i++) { bb[i] = (unsigned int)run; run += v[i]; }
        uint4 o;
        o.x = bb[0] | (bb[1] << 16); o.y = bb[2] | (bb[3] << 16);
        o.z = bb[4] | (bb[5] << 16); o.w = bb[6] | (bb[7] << 16);
        ((uint4*)(g_rbase + r * NCHUNK))[lane] = o;
        if (lane == 31) rtot[r] = run;
    }
    __syncthreads();
    if (t < 32) {
        int a2 = rtot[2 * t], b2 = rtot[2 * t + 1];
        int s2 = a2 + b2;
        int x2 = s2;
        #pragma unroll
        for (int off = 1; off < 32; off <<= 1) {
            int n = __shfl_up_sync(0xffffffffu, x2, off);
            if (t >= off) x2 += n;
        }
        int rb = x2 - s2;
        g_rstart[2 * t + 1] = rb + a2;
        g_rstart[2 * t + 2] = rb + s2;
        if (t == 0) g_rstart[0] = 0;
    }
}

__global__ void kscatter2(const int* __restrict__ ei)
{
    __shared__ int segs[CHUNK];
    __shared__ int rels[CHUNK];
    const int c = blockIdx.x;
    const int t = threadIdx.x;
    const int e = c * CHUNK + t;
    const int b = ei[e], hn = ei[Ee + e], tn = ei[2 * Ee + e], r = ei[3 * Ee + e];
    const int s = b * Nn + hn;
    segs[t] = s;
    rels[t] = r;
    __syncthreads();
    int rank = 0, rrank = 0;
    for (int i = 0; i < t; i++) {
        rank  += (segs[i] == s);
        rrank += (rels[i] == r);
    }
    int pos = g_start[s] + (int)g_base[s * NCHUNK + c] + rank;
    g_spos[e] = pos;
    g_voff[pos] = (b * Nn + tn) * HIDD;
    g_rsorted[g_rstart[r] + (int)g_rbase[r * NCHUNK + c] + rrank] = e;
}

// ---------------- 3) relation-batched logits on tensor cores ----------------
// cp.async groups: [R tiles] [A gathers] [K gathers]; MMA waits only on R+A,
// the 32KB K tile lands during the MMA loop and is consumed in the epilogue.
#define RSTR 72   // bf16 elem stride (144B rows -> conflict-free ldmatrix)
#define KSTR 68   // f32 elem stride
#define EDGE_SMEM (18432 + 18432 + 34816 + 9216 + 9216 + 192)
__global__ __launch_bounds__(256) void kedge2(const int* __restrict__ ei)
{
    extern __shared__ __align__(16) char sm[];
    __nv_bfloat16* sAh = (__nv_bfloat16*)(sm);
    __nv_bfloat16* sAl = (__nv_bfloat16*)(sm + 18432);
    float*         sK  = (float*)(sm + 36864);
    __nv_bfloat16* sRh = (__nv_bfloat16*)(sm + 71680);
    __nv_bfloat16* sRl = (__nv_bfloat16*)(sm + 80896);
    int* qoff = (int*)(sm + 90112);
    int* koff = qoff + 12;
    int* spv  = koff + 12;

    const int r  = blockIdx.x;
    const int t  = threadIdx.x;
    const int rs = g_rstart[r];
    const int total = (g_rstart[r + 1] - rs) * Hh;
    const int j0 = blockIdx.y * 128;
    if (j0 >= total) return;

    const uint32_t sAh_b = smem_u32(sAh), sAl_b = smem_u32(sAl);
    const uint32_t sRh_b = smem_u32(sRh), sRl_b = smem_u32(sRl);
    const uint32_t sK_b  = smem_u32(sK);

    // group A: R tile loads (independent of edge offsets) — issue first
    {
        const __nv_bfloat16* Rh = g_Rhi + (r << 12);
        const __nv_bfloat16* Rl = g_Rlo + (r << 12);
        #pragma unroll
        for (int i = t; i < 512; i += 256) {
            int n = i >> 3, f = i & 7;
            uint32_t soff = (uint32_t)(n * RSTR + f * 8) * 2;
            cp16(sRh_b + soff, Rh + n * 64 + f * 8);
            cp16(sRl_b + soff, Rl + n * 64 + f * 8);
        }
        CPCOMMIT();
    }

    const int e_first = j0 / Hh;
    const int jlast = min(j0 + 127, total - 1);
    const int nloc = jlast / Hh - e_first + 1;       // <= 12

    if (t < nloc) {
        int e = g_rsorted[rs + e_first + t];
        int b = ei[e], hn = ei[Ee + e], tn = ei[2 * Ee + e];
        qoff[t] = (b * Nn + hn) * HIDD;
        koff[t] = (b * Nn + tn) * HIDD;
        spv[t]  = g_spos[e];
    }
    __syncthreads();

    // group B: gather A (hi/lo) rows via cp.async
    #pragma unroll
    for (int i = t; i < 1024; i += 256) {
        int row = i >> 3, f = i & 7;
        int j = j0 + row; if (j > total - 1) j = total - 1;
        int le = j / Hh - e_first;
        int h = j % Hh;
        int off = qoff[le] + h * 64 + f * 8;
        uint32_t soff = (uint32_t)(row * RSTR + f * 8) * 2;
        cp16(sAh_b + soff, g_Qhi + off);
        cp16(sAl_b + soff, g_Qlo + off);
    }
    CPCOMMIT();

    // group C: gather K rows via cp.async (consumed only in the epilogue)
    #pragma unroll
    for (int i = t; i < 2048; i += 256) {
        int row = i >> 4, f = i & 15;
        int j = j0 + row; if (j > total - 1) j = total - 1;
        int le = j / Hh - e_first;
        int h = j % Hh;
        cp16(sK_b + (uint32_t)(row * KSTR + f * 4) * 4, g_K + koff[le] + h * 64 + f * 4);
    }
    CPCOMMIT();

    // wait for R + A only; K stays in flight through the MMA loop
    CPWAIT1();
    __syncthreads();

    const int lane = t & 31;
    const int wm = t >> 5;          // warp -> rows wm*16..+15
    const int g = lane >> 3, rr = lane & 7;

    float acc[8][4];
    #pragma unroll
    for (int nt = 0; nt < 8; nt++)
        #pragma unroll
        for (int q = 0; q < 4; q++) acc[nt][q] = 0.f;

    #pragma unroll
    for (int ks = 0; ks < 4; ks++) {
        uint32_t bh[8][2], bl[8][2], af[4];
        const int bcol = ks * 16 + (g & 1) * 8;
        #pragma unroll
        for (int np = 0; np < 4; np++) {
            int brow = np * 16 + (g >> 1) * 8 + rr;
            uint32_t tmp[4];
            ldmx4(tmp, sRh_b + (uint32_t)(brow * RSTR + bcol) * 2);
            bh[2 * np][0] = tmp[0]; bh[2 * np][1] = tmp[1];
            bh[2 * np + 1][0] = tmp[2]; bh[2 * np + 1][1] = tmp[3];
            ldmx4(tmp, sRl_b + (uint32_t)(brow * RSTR + bcol) * 2);
            bl[2 * np][0] = tmp[0]; bl[2 * np][1] = tmp[1];
            bl[2 * np + 1][0] = tmp[2]; bl[2 * np + 1][1] = tmp[3];
        }
        const int acol = ks * 16 + (g >> 1) * 8;
        const int arow = wm * 16 + (g & 1) * 8 + rr;
        ldmx4(af, sAh_b + (uint32_t)(arow * RSTR + acol) * 2);
        #pragma unroll
        for (int nt = 0; nt < 8; nt++) {
            mma16816(acc[nt], af, bh[nt]);
            mma16816(acc[nt], af, bl[nt]);
        }
        ldmx4(af, sAl_b + (uint32_t)(arow * RSTR + acol) * 2);
        #pragma unroll
        for (int nt = 0; nt < 8; nt++)
            mma16816(acc[nt], af, bh[nt]);
    }

    // K tile must now be resident; barrier before cross-thread sK reads
    CPWAIT0();
    __syncthreads();

    // epilogue: dot Qp rows with K rows (fp32), write at segment-sorted position
    const int rlo = wm * 16 + (lane >> 2);
    const int rhi = rlo + 8;
    float slo = 0.f, shi = 0.f;
    #pragma unroll
    for (int nt = 0; nt < 8; nt++) {
        int col = nt * 8 + (lane & 3) * 2;
        slo += acc[nt][0] * sK[rlo * KSTR + col] + acc[nt][1] * sK[rlo * KSTR + col + 1];
        shi += acc[nt][2] * sK[rhi * KSTR + col] + acc[nt][3] * sK[rhi * KSTR + col + 1];
    }
    slo += __shfl_xor_sync(0xffffffffu, slo, 1);
    slo += __shfl_xor_sync(0xffffffffu, slo, 2);
    shi += __shfl_xor_sync(0xffffffffu, shi, 1);
    shi += __shfl_xor_sync(0xffffffffu, shi, 2);
    if ((lane & 3) == 0) {
        int j = j0 + rlo;
        if (j < total) {
            int le = j / Hh - e_first;
            g_logits[spv[le] * Hh + (j % Hh)] = slo * 0.125f;
        }
        j = j0 + rhi;
        if (j < total) {
            int le = j / Hh - e_first;
            g_logits[spv[le] * Hh + (j % Hh)] = shi * 0.125f;
        }
    }
}

// ---------------- 4) per-segment softmax + V aggregation (coalesced inputs) ----------------
__global__ __launch_bounds__(128) void kagg(float* __restrict__ out)
{
    __shared__ float    exb[CAP * Hh];   // 24 KB
    __shared__ int      voff[CAP];       // 2 KB
    __shared__ unsigned umax[Hh];
    __shared__ float    mx[Hh], dnm[Hh];

    const int s = blockIdx.x;
    const int t = threadIdx.x;
    const int beg = g_start[s];
    int cnt = g_start[s + 1] - beg;
    if (cnt > CAP) cnt = CAP;
    float* orow = out + s * HIDD;

    if (cnt == 0) {
        #pragma unroll
        for (int j = 0; j < 6; j++) orow[t + 128 * j] = 0.f;
        return;
    }

    if (t < Hh) umax[t] = 0u;
    __syncthreads();

    for (int i = t; i < cnt; i += 128) voff[i] = g_voff[beg + i];
    const float* lsrc = g_logits + (long)beg * Hh;
    for (int j = t; j < cnt * Hh; j += 128) {
        float l = lsrc[j];
        exb[j] = l;
        int h = j % Hh;
        unsigned bits = __float_as_uint(l);
        unsigned key  = (bits & 0x80000000u) ? ~bits : (bits | 0x80000000u);
        atomicMax(&umax[h], key);   // order-independent -> deterministic
    }
    __syncthreads();

    if (t < Hh) {
        unsigned key  = umax[t];
        unsigned bits = (key & 0x80000000u) ? (key & 0x7fffffffu) : ~key;
        mx[t] = __uint_as_float(bits);
    }
    __syncthreads();

    for (int j = t; j < cnt * Hh; j += 128) {
        int h = j % Hh;
        exb[j] = __expf(exb[j] - mx[h]);
    }
    __syncthreads();

    const int w = t >> 5, lane = t & 31;
    #pragma unroll
    for (int jj = 0; jj < 3; jj++) {
        int h = w * 3 + jj;
        float p = 0.f;
        for (int i = lane; i < cnt; i += 32) p += exb[i * Hh + h];
        #pragma unroll
        for (int off = 16; off; off >>= 1) p += __shfl_xor_sync(0xffffffffu, p, off);
        if (lane == 0) dnm[h] = p;
    }
    __syncthreads();

    float rd[6], accr[6];
    int hcol[6];
    #pragma unroll
    for (int j = 0; j < 6; j++) {
        int c = t + 128 * j;
        hcol[j] = c >> 6;
        rd[j] = 1.f / dnm[hcol[j]];
        accr[j] = 0.f;
    }
    #pragma unroll 2
    for (int i = 0; i < cnt; i++) {
        const float* vrow = g_V + voff[i];
        const float* exr  = &exb[i * Hh];
        #pragma unroll
        for (int j = 0; j < 6; j++) {
            float p = exr[hcol[j]] * rd[j];
            accr[j] += p * vrow[t + 128 * j];
        }
    }
    #pragma unroll
    for (int j = 0; j < 6; j++) orow[t + 128 * j] = accr[j];
}

// ---------------- launch ----------------
extern "C" void kernel_launch(void* const* d_in, const int* in_sizes, int n_in,
                              void* d_out, int out_size)
{
    const float* node_states = (const float*)d_in[0];
    const int*   edge_idx    = (const int*)  d_in[1];
    // d_in[2] = node_type_ids (unused)
    const float* Wq = (const float*)d_in[3];
    const float* bq = (const float*)d_in[4];
    const float* Wk = (const float*)d_in[5];
    const float* bk = (const float*)d_in[6];
    const float* Wv = (const float*)d_in[7];
    const float* bv = (const float*)d_in[8];
    const float* rel = (const float*)d_in[9];
    float* out = (float*)d_out;

    static cudaStream_t s1 = nullptr;
    static cudaEvent_t evRoot = nullptr, evSort = nullptr;
    static bool init_done = false;
    if (!init_done) {
        cudaFuncSetAttribute(kedge2, cudaFuncAttributeMaxDynamicSharedMemorySize, EDGE_SMEM);
        cudaFuncSetAttribute(qkv_hmma, cudaFuncAttributeMaxDynamicSharedMemorySize, QKV_SMEM);
        cudaStreamCreateWithFlags(&s1, cudaStreamNonBlocking);
        cudaEventCreateWithFlags(&evRoot, cudaEventDisableTiming);
        cudaEventCreateWithFlags(&evSort, cudaEventDisableTiming);
        init_done = true;
    }

    // ---- fork: R-conv + sort chain on s1; X/W-conv + full QKV on main ----
    cudaEventRecord(evRoot, 0);
    cudaStreamWaitEvent(s1, evRoot, 0);

    // s1: R^T conversion (only needed by kedge2) + deterministic counting sorts
    kconvR<<<(NREL * 4096) / 256, 256, 0, s1>>>(rel);
    khist2<<<NCHUNK, 256, 0, s1>>>(edge_idx);
    kbasewarp2<<<NSEG / 8, 256, 0, s1>>>();
    kscan_all<<<1, 1024, 0, s1>>>();
    kscatter2<<<NCHUNK, CHUNK, 0, s1>>>(edge_idx);
    cudaEventRecord(evSort, s1);

    // main: split-bf16 conversion of X, W
    kconv<<<(XN + 3 * WN) / 256, 256>>>(node_states, Wq, Wk, Wv);

    // main: Q,K,V projections (288 blocks -> one full concurrent wave)
    qkv_hmma<<<dim3(6, 16, 3), 256, QKV_SMEM>>>(bq, bk, bv);

    // join sort(+R conv), then relation-batched logits
    cudaStreamWaitEvent(0, evSort, 0);
    kedge2<<<dim3(NREL, 120), 256, EDGE_SMEM>>>(edge_idx);

    // per-segment softmax + aggregation
    kagg<<<NSEG, 128>>>(out);
}

// round 14
// speedup vs baseline: 1.1039x; 1.0613x over previous
#include <cuda_runtime.h>
#include <cuda_bf16.h>
#include <cstdint>

// Problem geometry (fixed)
#define Bb    4
#define Nn    512
#define Hh    12
#define Dh    64
#define HIDD  768
#define Ee    65536
#define NSEG  2048          // Bb*Nn segments
#define NREL  64
#define NCHUNK 256
#define CHUNK  256          // NCHUNK*CHUNK == Ee
#define CAP    512          // max edges per segment handled

#define XN (2048*768)
#define WN (768*768)

// ---------------- device scratch (static; no allocations allowed) ----------------
__device__ float g_K[NSEG * HIDD];
__device__ float g_V[NSEG * HIDD];
__device__ float g_logits[Ee * Hh];          // stored in SEGMENT-SORTED edge order
__device__ unsigned short g_hist[NSEG * NCHUNK];   // [s][c]
__device__ unsigned short g_base[NSEG * NCHUNK];   // [s][c]
__device__ int   g_cnt[NSEG];
__device__ int   g_start[NSEG + 1];
__device__ int   g_spos[Ee];                 // edge -> position in segment order
__device__ int   g_voff[Ee];                 // segment-ordered V row offsets
// relation sort
__device__ unsigned short g_rhist[NREL * NCHUNK];  // [r][c]
__device__ unsigned short g_rbase[NREL * NCHUNK];  // [r][c]
__device__ int   g_rstart[NREL + 1];
__device__ int   g_rsorted[Ee];
// split-bf16 operands
__device__ __nv_bfloat16 g_Xhi[XN];
__device__ __nv_bfloat16 g_Xlo[XN];
__device__ __nv_bfloat16 g_Whi[3 * WN];
__device__ __nv_bfloat16 g_Wlo[3 * WN];
__device__ __nv_bfloat16 g_Qhi[NSEG * HIDD];
__device__ __nv_bfloat16 g_Qlo[NSEG * HIDD];
__device__ __nv_bfloat16 g_Rhi[NREL * 4096];   // transposed: [r][n][k]
__device__ __nv_bfloat16 g_Rlo[NREL * 4096];

// ---------------- helpers ----------------
__device__ __forceinline__ uint32_t smem_u32(const void* p) {
    uint32_t a;
    asm("{ .reg .u64 t; cvta.to.shared.u64 t, %1; cvt.u32.u64 %0, t; }" : "=r"(a) : "l"(p));
    return a;
}
__device__ __forceinline__ void ldmx4(uint32_t* r, uint32_t addr) {
    asm volatile("ldmatrix.sync.aligned.m8n8.x4.shared.b16 {%0,%1,%2,%3}, [%4];"
                 : "=r"(r[0]), "=r"(r[1]), "=r"(r[2]), "=r"(r[3]) : "r"(addr));
}
__device__ __forceinline__ void mma16816(float* c, const uint32_t* a, const uint32_t* b) {
    asm volatile("mma.sync.aligned.m16n8k16.row.col.f32.bf16.bf16.f32 "
                 "{%0,%1,%2,%3}, {%4,%5,%6,%7}, {%8,%9}, {%0,%1,%2,%3};"
                 : "+f"(c[0]), "+f"(c[1]), "+f"(c[2]), "+f"(c[3])
                 : "r"(a[0]), "r"(a[1]), "r"(a[2]), "r"(a[3]), "r"(b[0]), "r"(b[1]));
}
__device__ __forceinline__ void cp16(uint32_t dst, const void* src) {
    asm volatile("cp.async.cg.shared.global [%0], [%1], 16;" :: "r"(dst), "l"(src));
}
#define CPCOMMIT() asm volatile("cp.async.commit_group;" ::: "memory")
#define CPWAIT0()  asm volatile("cp.async.wait_group 0;" ::: "memory")

// ---------------- 0) split-bf16 conversion (X, W, R^T) ----------------
__global__ void kconv(const float* __restrict__ x,
                      const float* __restrict__ wq, const float* __restrict__ wk,
                      const float* __restrict__ wv, const float* __restrict__ rel)
{
    int i = blockIdx.x * 256 + threadIdx.x;
    float v; __nv_bfloat16* hi; __nv_bfloat16* lo; int o;
    if (i < XN) {
        v = x[i]; hi = g_Xhi; lo = g_Xlo; o = i;
    } else if (i < XN + 3 * WN) {
        int j = i - XN;
        int w = j / WN; o = j - w * WN;
        v = (w == 0 ? wq : (w == 1 ? wk : wv))[o];
        hi = g_Whi + w * WN; lo = g_Wlo + w * WN;
    } else {
        int j = i - XN - 3 * WN;          // 0..NREL*4096
        int r = j >> 12;
        int rem = j & 4095;
        int kk = rem >> 6;
        int nn = rem & 63;
        v = rel[j];
        o = (r << 12) + nn * 64 + kk;     // transposed store
        hi = g_Rhi; lo = g_Rlo;
    }
    __nv_bfloat16 h = __float2bfloat16(v);
    hi[o] = h;
    lo[o] = __float2bfloat16(v - __bfloat162float(h));
}

// ---------------- 1) QKV projection: mma.sync split-bf16, cp.async 2-stage ----------------
#define ASTR 40                 // padded bf16 row stride
#define QBUF (128 * ASTR * 2)   // bytes per operand buffer (10240)
#define QSTG (4 * QBUF)         // bytes per stage (40960)
#define QKV_SMEM (2 * QSTG)     // 81920
__global__ __launch_bounds__(256, 2) void qkv_hmma(
    const float* __restrict__ bq, const float* __restrict__ bk, const float* __restrict__ bv)
{
    extern __shared__ __align__(16) char qsm[];
    const int t = threadIdx.x;
    const int lane = t & 31;
    const int wid = t >> 5;
    const int wr = wid >> 2;        // 0..1  -> 64-row band
    const int wc = wid & 3;         // 0..3  -> 32-col band
    const int n0 = blockIdx.x * 128;
    const int m0 = blockIdx.y * 128;
    const int z  = blockIdx.z;

    const __nv_bfloat16* Wh = g_Whi + z * WN;
    const __nv_bfloat16* Wl = g_Wlo + z * WN;
    const uint32_t sbase = smem_u32(qsm);

    const int lrow0 = t >> 2;            // iter j: row = lrow0 + 64*j
    const int lf4   = t & 3;

    // preload chunk 0
    {
        #pragma unroll
        for (int j = 0; j < 2; j++) {
            int row = lrow0 + 64 * j;
            long goff = (long)row * HIDD + lf4 * 8;
            uint32_t soff = (uint32_t)(row * ASTR + lf4 * 8) * 2;
            cp16(sbase + 0 * QBUF + soff, g_Xhi + (long)m0 * HIDD + goff);
            cp16(sbase + 1 * QBUF + soff, g_Xlo + (long)m0 * HIDD + goff);
            cp16(sbase + 2 * QBUF + soff, Wh + (long)n0 * HIDD + goff);
            cp16(sbase + 3 * QBUF + soff, Wl + (long)n0 * HIDD + goff);
        }
        CPCOMMIT();
    }

    float acc[4][4][4];
    #pragma unroll
    for (int mi = 0; mi < 4; mi++)
        #pragma unroll
        for (int nj = 0; nj < 4; nj++)
            #pragma unroll
            for (int q = 0; q < 4; q++) acc[mi][nj][q] = 0.f;

    const int g  = lane >> 3;       // octet id 0..3
    const int rr = lane & 7;

    for (int kc = 0; kc < 24; kc++) {
        CPWAIT0();
        __syncthreads();
        if (kc < 23) {
            const int k0 = (kc + 1) * 32;
            const uint32_t stg = sbase + ((kc + 1) & 1) * QSTG;
            #pragma unroll
            for (int j = 0; j < 2; j++) {
                int row = lrow0 + 64 * j;
                long goff = (long)row * HIDD + k0 + lf4 * 8;
                uint32_t soff = (uint32_t)(row * ASTR + lf4 * 8) * 2;
                cp16(stg + 0 * QBUF + soff, g_Xhi + (long)m0 * HIDD + goff);
                cp16(stg + 1 * QBUF + soff, g_Xlo + (long)m0 * HIDD + goff);
                cp16(stg + 2 * QBUF + soff, Wh + (long)n0 * HIDD + goff);
                cp16(stg + 3 * QBUF + soff, Wl + (long)n0 * HIDD + goff);
            }
            CPCOMMIT();
        }

        const uint32_t cs = sbase + (kc & 1) * QSTG;
        const uint32_t sAh_b = cs;
        const uint32_t sAl_b = cs + QBUF;
        const uint32_t sBh_b = cs + 2 * QBUF;
        const uint32_t sBl_b = cs + 3 * QBUF;

        #pragma unroll
        for (int ks = 0; ks < 2; ks++) {
            uint32_t af[4][4], bh[4][2], bl[4][2];
            const int acol = ks * 16 + (g >> 1) * 8;
            #pragma unroll
            for (int mi = 0; mi < 4; mi++) {
                int arow = wr * 64 + mi * 16 + (g & 1) * 8 + rr;
                ldmx4(af[mi], sAh_b + (uint32_t)(arow * ASTR + acol) * 2);
            }
            const int bcol = ks * 16 + (g & 1) * 8;
            #pragma unroll
            for (int np = 0; np < 2; np++) {
                int brow = wc * 32 + np * 16 + (g >> 1) * 8 + rr;
                uint32_t tmp[4];
                ldmx4(tmp, sBh_b + (uint32_t)(brow * ASTR + bcol) * 2);
                bh[2 * np][0] = tmp[0]; bh[2 * np][1] = tmp[1];
                bh[2 * np + 1][0] = tmp[2]; bh[2 * np + 1][1] = tmp[3];
                ldmx4(tmp, sBl_b + (uint32_t)(brow * ASTR + bcol) * 2);
                bl[2 * np][0] = tmp[0]; bl[2 * np][1] = tmp[1];
                bl[2 * np + 1][0] = tmp[2]; bl[2 * np + 1][1] = tmp[3];
            }
            #pragma unroll
            for (int mi = 0; mi < 4; mi++)
                #pragma unroll
                for (int nj = 0; nj < 4; nj++) {
                    mma16816(acc[mi][nj], af[mi], bh[nj]);
                    mma16816(acc[mi][nj], af[mi], bl[nj]);
                }
            #pragma unroll
            for (int mi = 0; mi < 4; mi++) {
                int arow = wr * 64 + mi * 16 + (g & 1) * 8 + rr;
                ldmx4(af[mi], sAl_b + (uint32_t)(arow * ASTR + acol) * 2);
            }
            #pragma unroll
            for (int mi = 0; mi < 4; mi++)
                #pragma unroll
                for (int nj = 0; nj < 4; nj++)
                    mma16816(acc[mi][nj], af[mi], bh[nj]);
        }
    }

    // epilogue
    const float* bias = (z == 0) ? bq : (z == 1) ? bk : bv;
    #pragma unroll
    for (int mi = 0; mi < 4; mi++) {
        int row = m0 + wr * 64 + mi * 16 + (lane >> 2);
        #pragma unroll
        for (int nj = 0; nj < 4; nj++) {
            int col = n0 + wc * 32 + nj * 8 + (lane & 3) * 2;
            float b0 = bias[col], b1 = bias[col + 1];
            float v00 = acc[mi][nj][0] + b0, v01 = acc[mi][nj][1] + b1;
            float v10 = acc[mi][nj][2] + b0, v11 = acc[mi][nj][3] + b1;
            if (z == 0) {
                __nv_bfloat16 h00 = __float2bfloat16(v00), h01 = __float2bfloat16(v01);
                __nv_bfloat16 h10 = __float2bfloat16(v10), h11 = __float2bfloat16(v11);
                __nv_bfloat162 hi0; hi0.x = h00; hi0.y = h01;
                __nv_bfloat162 hi1; hi1.x = h10; hi1.y = h11;
                __nv_bfloat162 lo0; lo0.x = __float2bfloat16(v00 - __bfloat162float(h00));
                                    lo0.y = __float2bfloat16(v01 - __bfloat162float(h01));
                __nv_bfloat162 lo1; lo1.x = __float2bfloat16(v10 - __bfloat162float(h10));
                                    lo1.y = __float2bfloat16(v11 - __bfloat162float(h11));
                *(__nv_bfloat162*)(g_Qhi + (long)row * HIDD + col) = hi0;
                *(__nv_bfloat162*)(g_Qhi + (long)(row + 8) * HIDD + col) = hi1;
                *(__nv_bfloat162*)(g_Qlo + (long)row * HIDD + col) = lo0;
                *(__nv_bfloat162*)(g_Qlo + (long)(row + 8) * HIDD + col) = lo1;
            } else {
                float* outp = (z == 1) ? g_K : g_V;
                *(float2*)(outp + (long)row * HIDD + col) = make_float2(v00, v01);
                *(float2*)(outp + (long)(row + 8) * HIDD + col) = make_float2(v10, v11);
            }
        }
    }
}

// ---------------- 2) deterministic counting sorts (fused, transposed layouts) ----------------
__global__ void khist2(const int* __restrict__ ei)
{
    __shared__ int cnt[NSEG];
    __shared__ int rcnt[NREL];
    const int c = blockIdx.x;
    const int t = threadIdx.x;
    for (int i = t; i < NSEG; i += 256) cnt[i] = 0;
    if (t < NREL) rcnt[t] = 0;
    __syncthreads();
    const int e = c * CHUNK + t;
    const int s = ei[e] * Nn + ei[Ee + e];
    atomicAdd(&cnt[s], 1);
    atomicAdd(&rcnt[ei[3 * Ee + e]], 1);
    __syncthreads();
    for (int i = t; i < NSEG; i += 256) g_hist[i * NCHUNK + c] = (unsigned short)cnt[i];
    if (t < NREL) g_rhist[t * NCHUNK + c] = (unsigned short)rcnt[t];
}

__global__ void kbasewarp2()
{
    const int t = threadIdx.x;
    const int s = blockIdx.x * 8 + (t >> 5);
    const int lane = t & 31;
    uint4 v4 = ((const uint4*)(g_hist + s * NCHUNK))[lane];
    int v[8] = { (int)(v4.x & 0xffff), (int)(v4.x >> 16), (int)(v4.y & 0xffff), (int)(v4.y >> 16),
                 (int)(v4.z & 0xffff), (int)(v4.z >> 16), (int)(v4.w & 0xffff), (int)(v4.w >> 16) };
    int sum = 0;
    #pragma unroll
    for (int i = 0; i < 8; i++) sum += v[i];
    int ex = sum;
    #pragma unroll
    for (int off = 1; off < 32; off <<= 1) {
        int n = __shfl_up_sync(0xffffffffu, ex, off);
        if (lane >= off) ex += n;
    }
    int run = ex - sum;
    unsigned int b[8];
    #pragma unroll
    for (int i = 0; i < 8; i++) { b[i] = (unsigned int)run; run += v[i]; }
    uint4 o;
    o.x = b[0] | (b[1] << 16); o.y = b[2] | (b[3] << 16);
    o.z = b[4] | (b[5] << 16); o.w = b[6] | (b[7] << 16);
    ((uint4*)(g_base + s * NCHUNK))[lane] = o;
    if (lane == 31) g_cnt[s] = run;
}

__global__ void kscan_all()
{
    __shared__ int wsum[32];
    __shared__ int rtot[NREL];
    const int t = threadIdx.x;   // 1024
    const int lane = t & 31, w = t >> 5;
    int a = g_cnt[2 * t], b = g_cnt[2 * t + 1];
    int s = a + b;
    int x = s;
    #pragma unroll
    for (int off = 1; off < 32; off <<= 1) {
        int n = __shfl_up_sync(0xffffffffu, x, off);
        if (lane >= off) x += n;
    }
    if (lane == 31) wsum[w] = x;
    __syncthreads();
    if (w == 0) {
        int y = wsum[lane];
        #pragma unroll
        for (int off = 1; off < 32; off <<= 1) {
            int n = __shfl_up_sync(0xffffffffu, y, off);
            if (lane >= off) y += n;
        }
        wsum[lane] = y;
    }
    __syncthreads();
    int base = (w ? wsum[w - 1] : 0) + x - s;
    g_start[2 * t + 1] = base + a;
    g_start[2 * t + 2] = base + a + b;
    if (t == 0) g_start[0] = 0;
    #pragma unroll
    for (int q = 0; q < 2; q++) {
        int r = w * 2 + q;
        uint4 v4 = ((const uint4*)(g_rhist + r * NCHUNK))[lane];
        int v[8] = { (int)(v4.x & 0xffff), (int)(v4.x >> 16), (int)(v4.y & 0xffff), (int)(v4.y >> 16),
                     (int)(v4.z & 0xffff), (int)(v4.z >> 16), (int)(v4.w & 0xffff), (int)(v4.w >> 16) };
        int sm2 = 0;
        #pragma unroll
        for (int i = 0; i < 8; i++) sm2 += v[i];
        int ex = sm2;
        #pragma unroll
        for (int off = 1; off < 32; off <<= 1) {
            int n = __shfl_up_sync(0xffffffffu, ex, off);
            if (lane >= off) ex += n;
        }
        int run = ex - sm2;
        unsigned int bb[8];
        #pragma unroll
        for (int i = 0; i < 8; i++) { bb[i] = (unsigned int)run; run += v[i]; }
        uint4 o;
        o.x = bb[0] | (bb[1] << 16); o.y = bb[2] | (bb[3] << 16);
        o.z = bb[4] | (bb[5] << 16); o.w = bb[6] | (bb[7] << 16);
        ((uint4*)(g_rbase + r * NCHUNK))[lane] = o;
        if (lane == 31) rtot[r] = run;
    }
    __syncthreads();
    if (t < 32) {
        int a2 = rtot[2 * t], b2 = rtot[2 * t + 1];
        int s2 = a2 + b2;
        int x2 = s2;
        #pragma unroll
        for (int off = 1; off < 32; off <<= 1) {
            int n = __shfl_up_sync(0xffffffffu, x2, off);
            if (t >= off) x2 += n;
        }
        int rb = x2 - s2;
        g_rstart[2 * t + 1] = rb + a2;
        g_rstart[2 * t + 2] = rb + s2;
        if (t == 0) g_rstart[0] = 0;
    }
}

__global__ void kscatter2(const int* __restrict__ ei)
{
    __shared__ int segs[CHUNK];
    __shared__ int rels[CHUNK];
    const int c = blockIdx.x;
    const int t = threadIdx.x;
    const int e = c * CHUNK + t;
    const int b = ei[e], hn = ei[Ee + e], tn = ei[2 * Ee + e], r = ei[3 * Ee + e];
    const int s = b * Nn + hn;
    segs[t] = s;
    rels[t] = r;
    __syncthreads();
    int rank = 0, rrank = 0;
    for (int i = 0; i < t; i++) {
        rank  += (segs[i] == s);
        rrank += (rels[i] == r);
    }
    int pos = g_start[s] + (int)g_base[s * NCHUNK + c] + rank;
    g_spos[e] = pos;
    g_voff[pos] = (b * Nn + tn) * HIDD;
    g_rsorted[g_rstart[r] + (int)g_rbase[r * NCHUNK + c] + rrank] = e;
}

// ---------------- 3) relation-batched logits on tensor cores (round-10 dataflow) ----------------
#define RSTR 72   // bf16 elem stride (144B rows -> conflict-free ldmatrix)
#define KSTR 68   // f32 elem stride
#define EDGE_SMEM (18432 + 18432 + 34816 + 9216 + 9216 + 192)
__global__ __launch_bounds__(256, 2) void kedge2(const int* __restrict__ ei)
{
    extern __shared__ __align__(16) char sm[];
    __nv_bfloat16* sAh = (__nv_bfloat16*)(sm);
    __nv_bfloat16* sAl = (__nv_bfloat16*)(sm + 18432);
    float*         sK  = (float*)(sm + 36864);
    __nv_bfloat16* sRh = (__nv_bfloat16*)(sm + 71680);
    __nv_bfloat16* sRl = (__nv_bfloat16*)(sm + 80896);
    int* qoff = (int*)(sm + 90112);
    int* koff = qoff + 12;
    int* spv  = koff + 12;

    const int r  = blockIdx.x;
    const int t  = threadIdx.x;
    const int rs = g_rstart[r];
    const int total = (g_rstart[r + 1] - rs) * Hh;
    const int j0 = blockIdx.y * 128;
    if (j0 >= total) return;

    const uint32_t sAh_b = smem_u32(sAh), sAl_b = smem_u32(sAl);
    const uint32_t sRh_b = smem_u32(sRh), sRl_b = smem_u32(sRl);
    const uint32_t sK_b  = smem_u32(sK);

    // R tile loads (independent of edge offsets) — issue first
    {
        const __nv_bfloat16* Rh = g_Rhi + (r << 12);
        const __nv_bfloat16* Rl = g_Rlo + (r << 12);
        #pragma unroll
        for (int i = t; i < 512; i += 256) {
            int n = i >> 3, f = i & 7;
            uint32_t soff = (uint32_t)(n * RSTR + f * 8) * 2;
            cp16(sRh_b + soff, Rh + n * 64 + f * 8);
            cp16(sRl_b + soff, Rl + n * 64 + f * 8);
        }
        CPCOMMIT();
    }

    const int e_first = j0 / Hh;
    const int jlast = min(j0 + 127, total - 1);
    const int nloc = jlast / Hh - e_first + 1;       // <= 12

    if (t < nloc) {
        int e = g_rsorted[rs + e_first + t];
        int b = ei[e], hn = ei[Ee + e], tn = ei[2 * Ee + e];
        qoff[t] = (b * Nn + hn) * HIDD;
        koff[t] = (b * Nn + tn) * HIDD;
        spv[t]  = g_spos[e];
    }
    __syncthreads();

    // gather A (hi/lo) rows and K rows via cp.async
    #pragma unroll
    for (int i = t; i < 1024; i += 256) {
        int row = i >> 3, f = i & 7;
        int j = j0 + row; if (j > total - 1) j = total - 1;
        int le = j / Hh - e_first;
        int h = j % Hh;
        int off = qoff[le] + h * 64 + f * 8;
        uint32_t soff = (uint32_t)(row * RSTR + f * 8) * 2;
        cp16(sAh_b + soff, g_Qhi + off);
        cp16(sAl_b + soff, g_Qlo + off);
    }
    #pragma unroll
    for (int i = t; i < 2048; i += 256) {
        int row = i >> 4, f = i & 15;
        int j = j0 + row; if (j > total - 1) j = total - 1;
        int le = j / Hh - e_first;
        int h = j % Hh;
        cp16(sK_b + (uint32_t)(row * KSTR + f * 4) * 4, g_K + koff[le] + h * 64 + f * 4);
    }
    CPCOMMIT();
    CPWAIT0();
    __syncthreads();

    const int lane = t & 31;
    const int wm = t >> 5;          // warp -> rows wm*16..+15
    const int g = lane >> 3, rr = lane & 7;

    float acc[8][4];
    #pragma unroll
    for (int nt = 0; nt < 8; nt++)
        #pragma unroll
        for (int q = 0; q < 4; q++) acc[nt][q] = 0.f;

    #pragma unroll
    for (int ks = 0; ks < 4; ks++) {
        uint32_t bh[8][2], bl[8][2], af[4];
        const int bcol = ks * 16 + (g & 1) * 8;
        #pragma unroll
        for (int np = 0; np < 4; np++) {
            int brow = np * 16 + (g >> 1) * 8 + rr;
            uint32_t tmp[4];
            ldmx4(tmp, sRh_b + (uint32_t)(brow * RSTR + bcol) * 2);
            bh[2 * np][0] = tmp[0]; bh[2 * np][1] = tmp[1];
            bh[2 * np + 1][0] = tmp[2]; bh[2 * np + 1][1] = tmp[3];
            ldmx4(tmp, sRl_b + (uint32_t)(brow * RSTR + bcol) * 2);
            bl[2 * np][0] = tmp[0]; bl[2 * np][1] = tmp[1];
            bl[2 * np + 1][0] = tmp[2]; bl[2 * np + 1][1] = tmp[3];
        }
        const int acol = ks * 16 + (g >> 1) * 8;
        const int arow = wm * 16 + (g & 1) * 8 + rr;
        ldmx4(af, sAh_b + (uint32_t)(arow * RSTR + acol) * 2);
        #pragma unroll
        for (int nt = 0; nt < 8; nt++) {
            mma16816(acc[nt], af, bh[nt]);
            mma16816(acc[nt], af, bl[nt]);
        }
        ldmx4(af, sAl_b + (uint32_t)(arow * RSTR + acol) * 2);
        #pragma unroll
        for (int nt = 0; nt < 8; nt++)
            mma16816(acc[nt], af, bh[nt]);
    }

    // epilogue: dot Qp rows with K rows (fp32), write at segment-sorted position
    const int rlo = wm * 16 + (lane >> 2);
    const int rhi = rlo + 8;
    float slo = 0.f, shi = 0.f;
    #pragma unroll
    for (int nt = 0; nt < 8; nt++) {
        int col = nt * 8 + (lane & 3) * 2;
        slo += acc[nt][0] * sK[rlo * KSTR + col] + acc[nt][1] * sK[rlo * KSTR + col + 1];
        shi += acc[nt][2] * sK[rhi * KSTR + col] + acc[nt][3] * sK[rhi * KSTR + col + 1];
    }
    slo += __shfl_xor_sync(0xffffffffu, slo, 1);
    slo += __shfl_xor_sync(0xffffffffu, slo, 2);
    shi += __shfl_xor_sync(0xffffffffu, shi, 1);
    shi += __shfl_xor_sync(0xffffffffu, shi, 2);
    if ((lane & 3) == 0) {
        int j = j0 + rlo;
        if (j < total) {
            int le = j / Hh - e_first;
            g_logits[spv[le] * Hh + (j % Hh)] = slo * 0.125f;
        }
        j = j0 + rhi;
        if (j < total) {
            int le = j / Hh - e_first;
            g_logits[spv[le] * Hh + (j % Hh)] = shi * 0.125f;
        }
    }
}

// ---------------- 4) per-segment softmax + V aggregation (coalesced inputs) ----------------
__global__ __launch_bounds__(128) void kagg(float* __restrict__ out)
{
    __shared__ float    exb[CAP * Hh];   // 24 KB
    __shared__ int      voff[CAP];       // 2 KB
    __shared__ unsigned umax[Hh];
    __shared__ float    mx[Hh], dnm[Hh];

    const int s = blockIdx.x;
    const int t = threadIdx.x;
    const int beg = g_start[s];
    int cnt = g_start[s + 1] - beg;
    if (cnt > CAP) cnt = CAP;
    float* orow = out + s * HIDD;

    if (cnt == 0) {
        #pragma unroll
        for (int j = 0; j < 6; j++) orow[t + 128 * j] = 0.f;
        return;
    }

    if (t < Hh) umax[t] = 0u;
    __syncthreads();

    for (int i = t; i < cnt; i += 128) voff[i] = g_voff[beg + i];
    const float* lsrc = g_logits + (long)beg * Hh;
    for (int j = t; j < cnt * Hh; j += 128) {
        float l = lsrc[j];
        exb[j] = l;
        int h = j % Hh;
        unsigned bits = __float_as_uint(l);
        unsigned key  = (bits & 0x80000000u) ? ~bits : (bits | 0x80000000u);
        atomicMax(&umax[h], key);   // order-independent -> deterministic
    }
    __syncthreads();

    if (t < Hh) {
        unsigned key  = umax[t];
        unsigned bits = (key & 0x80000000u) ? (key & 0x7fffffffu) : ~key;
        mx[t] = __uint_as_float(bits);
    }
    __syncthreads();

    for (int j = t; j < cnt * Hh; j += 128) {
        int h = j % Hh;
        exb[j] = __expf(exb[j] - mx[h]);
    }
    __syncthreads();

    const int w = t >> 5, lane = t & 31;
    #pragma unroll
    for (int jj = 0; jj < 3; jj++) {
        int h = w * 3 + jj;
        float p = 0.f;
        for (int i = lane; i < cnt; i += 32) p += exb[i * Hh + h];
        #pragma unroll
        for (int off = 16; off; off >>= 1) p += __shfl_xor_sync(0xffffffffu, p, off);
        if (lane == 0) dnm[h] = p;
    }
    __syncthreads();

    float rd[6], accr[6];
    int hcol[6];
    #pragma unroll
    for (int j = 0; j < 6; j++) {
        int c = t + 128 * j;
        hcol[j] = c >> 6;
        rd[j] = 1.f / dnm[hcol[j]];
        accr[j] = 0.f;
    }
    #pragma unroll 2
    for (int i = 0; i < cnt; i++) {
        const float* vrow = g_V + voff[i];
        const float* exr  = &exb[i * Hh];
        #pragma unroll
        for (int j = 0; j < 6; j++) {
            float p = exr[hcol[j]] * rd[j];
            accr[j] += p * vrow[t + 128 * j];
        }
    }
    #pragma unroll
    for (int j = 0; j < 6; j++) orow[t + 128 * j] = accr[j];
}

// ---------------- launch ----------------
extern "C" void kernel_launch(void* const* d_in, const int* in_sizes, int n_in,
                              void* d_out, int out_size)
{
    const float* node_states = (const float*)d_in[0];
    const int*   edge_idx    = (const int*)  d_in[1];
    // d_in[2] = node_type_ids (unused)
    const float* Wq = (const float*)d_in[3];
    const float* bq = (const float*)d_in[4];
    const float* Wk = (const float*)d_in[5];
    const float* bk = (const float*)d_in[6];
    const float* Wv = (const float*)d_in[7];
    const float* bv = (const float*)d_in[8];
    const float* rel = (const float*)d_in[9];
    float* out = (float*)d_out;

    static cudaStream_t s1 = nullptr;
    static cudaEvent_t evRoot = nullptr, evSort = nullptr;
    static bool init_done = false;
    if (!init_done) {
        cudaFuncSetAttribute(kedge2, cudaFuncAttributeMaxDynamicSharedMemorySize, EDGE_SMEM);
        cudaFuncSetAttribute(qkv_hmma, cudaFuncAttributeMaxDynamicSharedMemorySize, QKV_SMEM);
        cudaStreamCreateWithFlags(&s1, cudaStreamNonBlocking);
        cudaEventCreateWithFlags(&evRoot, cudaEventDisableTiming);
        cudaEventCreateWithFlags(&evSort, cudaEventDisableTiming);
        init_done = true;
    }

    // ---- minimal fork: sort chain on s1, everything else on main ----
    cudaEventRecord(evRoot, 0);
    cudaStreamWaitEvent(s1, evRoot, 0);

    // s1: deterministic counting sorts (independent of conversions/GEMMs)
    khist2<<<NCHUNK, 256, 0, s1>>>(edge_idx);
    kbasewarp2<<<NSEG / 8, 256, 0, s1>>>();
    kscan_all<<<1, 1024, 0, s1>>>();
    kscatter2<<<NCHUNK, CHUNK, 0, s1>>>(edge_idx);
    cudaEventRecord(evSort, s1);

    // main: split-bf16 conversion of X, W, R^T
    kconv<<<(XN + 3 * WN + NREL * 4096) / 256, 256>>>(node_states, Wq, Wk, Wv, rel);

    // main: Q,K,V projections (288 blocks -> one full concurrent wave)
    qkv_hmma<<<dim3(6, 16, 3), 256, QKV_SMEM>>>(bq, bk, bv);

    // join sort, then relation-batched logits
    cudaStreamWaitEvent(0, evSort, 0);
    kedge2<<<dim3(NREL, 120), 256, EDGE_SMEM>>>(edge_idx);

    // per-segment softmax + aggregation
    kagg<<<NSEG, 128>>>(out);
}

// round 17
// speedup vs baseline: 1.1547x; 1.0460x over previous
#include <cuda_runtime.h>
#include <cuda_bf16.h>
#include <cstdint>

// Problem geometry (fixed)
#define Bb    4
#define Nn    512
#define Hh    12
#define Dh    64
#define HIDD  768
#define Ee    65536
#define NSEG  2048          // Bb*Nn segments
#define NREL  64
#define NCHUNK 256
#define CHUNK  256          // NCHUNK*CHUNK == Ee
#define CAP    512          // max edges per segment handled

#define XN (2048*768)
#define WN (768*768)

// ---------------- device scratch (static; no allocations allowed) ----------------
__device__ float g_K[NSEG * HIDD];
__device__ float g_V[NSEG * HIDD];
__device__ float g_logits[Ee * Hh];          // stored in SEGMENT-SORTED edge order
__device__ unsigned short g_hist[NSEG * NCHUNK];   // [s][c]
__device__ unsigned short g_base[NSEG * NCHUNK];   // [s][c]
__device__ int   g_cnt[NSEG];
__device__ int   g_start[NSEG + 1];
__device__ int   g_spos[Ee];                 // edge -> position in segment order
__device__ int   g_voff[Ee];                 // segment-ordered V row offsets
// relation sort
__device__ unsigned short g_rhist[NREL * NCHUNK];  // [r][c]
__device__ unsigned short g_rbase[NREL * NCHUNK];  // [r][c]
__device__ int   g_rstart[NREL + 1];
__device__ int   g_rsorted[Ee];
// split-bf16 operands
__device__ __nv_bfloat16 g_Xhi[XN];
__device__ __nv_bfloat16 g_Xlo[XN];
__device__ __nv_bfloat16 g_Whi[3 * WN];
__device__ __nv_bfloat16 g_Wlo[3 * WN];
__device__ __nv_bfloat16 g_Qhi[NSEG * HIDD];
__device__ __nv_bfloat16 g_Qlo[NSEG * HIDD];
__device__ __nv_bfloat16 g_Rhi[NREL * 4096];   // transposed: [r][n][k]
__device__ __nv_bfloat16 g_Rlo[NREL * 4096];

// ---------------- helpers ----------------
__device__ __forceinline__ uint32_t smem_u32(const void* p) {
    uint32_t a;
    asm("{ .reg .u64 t; cvta.to.shared.u64 t, %1; cvt.u32.u64 %0, t; }" : "=r"(a) : "l"(p));
    return a;
}
__device__ __forceinline__ void ldmx4(uint32_t* r, uint32_t addr) {
    asm volatile("ldmatrix.sync.aligned.m8n8.x4.shared.b16 {%0,%1,%2,%3}, [%4];"
                 : "=r"(r[0]), "=r"(r[1]), "=r"(r[2]), "=r"(r[3]) : "r"(addr));
}
__device__ __forceinline__ void mma16816(float* c, const uint32_t* a, const uint32_t* b) {
    asm volatile("mma.sync.aligned.m16n8k16.row.col.f32.bf16.bf16.f32 "
                 "{%0,%1,%2,%3}, {%4,%5,%6,%7}, {%8,%9}, {%0,%1,%2,%3};"
                 : "+f"(c[0]), "+f"(c[1]), "+f"(c[2]), "+f"(c[3])
                 : "r"(a[0]), "r"(a[1]), "r"(a[2]), "r"(a[3]), "r"(b[0]), "r"(b[1]));
}
__device__ __forceinline__ void cp16(uint32_t dst, const void* src) {
    asm volatile("cp.async.cg.shared.global [%0], [%1], 16;" :: "r"(dst), "l"(src));
}
#define CPCOMMIT() asm volatile("cp.async.commit_group;" ::: "memory")
#define CPWAIT0()  asm volatile("cp.async.wait_group 0;" ::: "memory")

__device__ __forceinline__ void split4(float4 v, __nv_bfloat16* hi, __nv_bfloat16* lo, int o) {
    __nv_bfloat16 h0 = __float2bfloat16(v.x), h1 = __float2bfloat16(v.y);
    __nv_bfloat16 h2 = __float2bfloat16(v.z), h3 = __float2bfloat16(v.w);
    __nv_bfloat162 hp0; hp0.x = h0; hp0.y = h1;
    __nv_bfloat162 hp1; hp1.x = h2; hp1.y = h3;
    __nv_bfloat162 lp0; lp0.x = __float2bfloat16(v.x - __bfloat162float(h0));
                        lp0.y = __float2bfloat16(v.y - __bfloat162float(h1));
    __nv_bfloat162 lp1; lp1.x = __float2bfloat16(v.z - __bfloat162float(h2));
                        lp1.y = __float2bfloat16(v.w - __bfloat162float(h3));
    *(__nv_bfloat162*)(hi + o)     = hp0;
    *(__nv_bfloat162*)(hi + o + 2) = hp1;
    *(__nv_bfloat162*)(lo + o)     = lp0;
    *(__nv_bfloat162*)(lo + o + 2) = lp1;
}

// ---------------- 0) split-bf16 conversion (X, W, R^T), float4-vectorized ----------------
#define CONVN ((XN + 3 * WN + NREL * 4096) / 4)
__global__ void kconv(const float* __restrict__ x,
                      const float* __restrict__ wq, const float* __restrict__ wk,
                      const float* __restrict__ wv, const float* __restrict__ rel)
{
    int i4 = blockIdx.x * 256 + threadIdx.x;   // index of a 4-element group
    if (i4 >= CONVN) return;
    int i = i4 * 4;
    if (i < XN) {
        split4(*(const float4*)(x + i), g_Xhi, g_Xlo, i);
    } else if (i < XN + 3 * WN) {
        int j = i - XN;
        int w = j / WN; int o = j - w * WN;
        const float* src = (w == 0 ? wq : (w == 1 ? wk : wv));
        split4(*(const float4*)(src + o), g_Whi + w * WN, g_Wlo + w * WN, o);
    } else {
        int j = i - XN - 3 * WN;          // 0..NREL*4096, 4 consecutive (same row kk)
        int r = j >> 12;
        int rem = j & 4095;
        int kk = rem >> 6;
        int nn = rem & 63;                // nn, nn+1, nn+2, nn+3
        float4 v = *(const float4*)(rel + j);
        int ob = (r << 12) + nn * 64 + kk;    // transposed: stride 64 between elements
        float vv[4] = {v.x, v.y, v.z, v.w};
        #pragma unroll
        for (int q = 0; q < 4; q++) {
            __nv_bfloat16 h = __float2bfloat16(vv[q]);
            g_Rhi[ob + q * 64] = h;
            g_Rlo[ob + q * 64] = __float2bfloat16(vv[q] - __bfloat162float(h));
        }
    }
}

// ---------------- 1) QKV projection: mma.sync split-bf16, cp.async 2-stage ----------------
#define ASTR 40                 // padded bf16 row stride
#define QBUF (128 * ASTR * 2)   // bytes per operand buffer (10240)
#define QSTG (4 * QBUF)         // bytes per stage (40960)
#define QKV_SMEM (2 * QSTG)     // 81920
__global__ __launch_bounds__(256, 2) void qkv_hmma(
    const float* __restrict__ bq, const float* __restrict__ bk, const float* __restrict__ bv)
{
    extern __shared__ __align__(16) char qsm[];
    const int t = threadIdx.x;
    const int lane = t & 31;
    const int wid = t >> 5;
    const int wr = wid >> 2;        // 0..1  -> 64-row band
    const int wc = wid & 3;         // 0..3  -> 32-col band
    const int n0 = blockIdx.x * 128;
    const int m0 = blockIdx.y * 128;
    const int z  = blockIdx.z;

    const __nv_bfloat16* Wh = g_Whi + z * WN;
    const __nv_bfloat16* Wl = g_Wlo + z * WN;
    const uint32_t sbase = smem_u32(qsm);

    const int lrow0 = t >> 2;            // iter j: row = lrow0 + 64*j
    const int lf4   = t & 3;

    // preload chunk 0
    {
        #pragma unroll
        for (int j = 0; j < 2; j++) {
            int row = lrow0 + 64 * j;
            long goff = (long)row * HIDD + lf4 * 8;
            uint32_t soff = (uint32_t)(row * ASTR + lf4 * 8) * 2;
            cp16(sbase + 0 * QBUF + soff, g_Xhi + (long)m0 * HIDD + goff);
            cp16(sbase + 1 * QBUF + soff, g_Xlo + (long)m0 * HIDD + goff);
            cp16(sbase + 2 * QBUF + soff, Wh + (long)n0 * HIDD + goff);
            cp16(sbase + 3 * QBUF + soff, Wl + (long)n0 * HIDD + goff);
        }
        CPCOMMIT();
    }

    float acc[4][4][4];
    #pragma unroll
    for (int mi = 0; mi < 4; mi++)
        #pragma unroll
        for (int nj = 0; nj < 4; nj++)
            #pragma unroll
            for (int q = 0; q < 4; q++) acc[mi][nj][q] = 0.f;

    const int g  = lane >> 3;       // octet id 0..3
    const int rr = lane & 7;

    for (int kc = 0; kc < 24; kc++) {
        CPWAIT0();
        __syncthreads();
        if (kc < 23) {
            const int k0 = (kc + 1) * 32;
            const uint32_t stg = sbase + ((kc + 1) & 1) * QSTG;
            #pragma unroll
            for (int j = 0; j < 2; j++) {
                int row = lrow0 + 64 * j;
                long goff = (long)row * HIDD + k0 + lf4 * 8;
                uint32_t soff = (uint32_t)(row * ASTR + lf4 * 8) * 2;
                cp16(stg + 0 * QBUF + soff, g_Xhi + (long)m0 * HIDD + goff);
                cp16(stg + 1 * QBUF + soff, g_Xlo + (long)m0 * HIDD + goff);
                cp16(stg + 2 * QBUF + soff, Wh + (long)n0 * HIDD + goff);
                cp16(stg + 3 * QBUF + soff, Wl + (long)n0 * HIDD + goff);
            }
            CPCOMMIT();
        }

        const uint32_t cs = sbase + (kc & 1) * QSTG;
        const uint32_t sAh_b = cs;
        const uint32_t sAl_b = cs + QBUF;
        const uint32_t sBh_b = cs + 2 * QBUF;
        const uint32_t sBl_b = cs + 3 * QBUF;

        #pragma unroll
        for (int ks = 0; ks < 2; ks++) {
            uint32_t af[4][4], bh[4][2], bl[4][2];
            const int acol = ks * 16 + (g >> 1) * 8;
            #pragma unroll
            for (int mi = 0; mi < 4; mi++) {
                int arow = wr * 64 + mi * 16 + (g & 1) * 8 + rr;
                ldmx4(af[mi], sAh_b + (uint32_t)(arow * ASTR + acol) * 2);
            }
            const int bcol = ks * 16 + (g & 1) * 8;
            #pragma unroll
            for (int np = 0; np < 2; np++) {
                int brow = wc * 32 + np * 16 + (g >> 1) * 8 + rr;
                uint32_t tmp[4];
                ldmx4(tmp, sBh_b + (uint32_t)(brow * ASTR + bcol) * 2);
                bh[2 * np][0] = tmp[0]; bh[2 * np][1] = tmp[1];
                bh[2 * np + 1][0] = tmp[2]; bh[2 * np + 1][1] = tmp[3];
                ldmx4(tmp, sBl_b + (uint32_t)(brow * ASTR + bcol) * 2);
                bl[2 * np][0] = tmp[0]; bl[2 * np][1] = tmp[1];
                bl[2 * np + 1][0] = tmp[2]; bl[2 * np + 1][1] = tmp[3];
            }
            #pragma unroll
            for (int mi = 0; mi < 4; mi++)
                #pragma unroll
                for (int nj = 0; nj < 4; nj++) {
                    mma16816(acc[mi][nj], af[mi], bh[nj]);
                    mma16816(acc[mi][nj], af[mi], bl[nj]);
                }
            #pragma unroll
            for (int mi = 0; mi < 4; mi++) {
                int arow = wr * 64 + mi * 16 + (g & 1) * 8 + rr;
                ldmx4(af[mi], sAl_b + (uint32_t)(arow * ASTR + acol) * 2);
            }
            #pragma unroll
            for (int mi = 0; mi < 4; mi++)
                #pragma unroll
                for (int nj = 0; nj < 4; nj++)
                    mma16816(acc[mi][nj], af[mi], bh[nj]);
        }
    }

    // epilogue
    const float* bias = (z == 0) ? bq : (z == 1) ? bk : bv;
    #pragma unroll
    for (int mi = 0; mi < 4; mi++) {
        int row = m0 + wr * 64 + mi * 16 + (lane >> 2);
        #pragma unroll
        for (int nj = 0; nj < 4; nj++) {
            int col = n0 + wc * 32 + nj * 8 + (lane & 3) * 2;
            float b0 = bias[col], b1 = bias[col + 1];
            float v00 = acc[mi][nj][0] + b0, v01 = acc[mi][nj][1] + b1;
            float v10 = acc[mi][nj][2] + b0, v11 = acc[mi][nj][3] + b1;
            if (z == 0) {
                __nv_bfloat16 h00 = __float2bfloat16(v00), h01 = __float2bfloat16(v01);
                __nv_bfloat16 h10 = __float2bfloat16(v10), h11 = __float2bfloat16(v11);
                __nv_bfloat162 hi0; hi0.x = h00; hi0.y = h01;
                __nv_bfloat162 hi1; hi1.x = h10; hi1.y = h11;
                __nv_bfloat162 lo0; lo0.x = __float2bfloat16(v00 - __bfloat162float(h00));
                                    lo0.y = __float2bfloat16(v01 - __bfloat162float(h01));
                __nv_bfloat162 lo1; lo1.x = __float2bfloat16(v10 - __bfloat162float(h10));
                                    lo1.y = __float2bfloat16(v11 - __bfloat162float(h11));
                *(__nv_bfloat162*)(g_Qhi + (long)row * HIDD + col) = hi0;
                *(__nv_bfloat162*)(g_Qhi + (long)(row + 8) * HIDD + col) = hi1;
                *(__nv_bfloat162*)(g_Qlo + (long)row * HIDD + col) = lo0;
                *(__nv_bfloat162*)(g_Qlo + (long)(row + 8) * HIDD + col) = lo1;
            } else {
                float* outp = (z == 1) ? g_K : g_V;
                *(float2*)(outp + (long)row * HIDD + col) = make_float2(v00, v01);
                *(float2*)(outp + (long)(row + 8) * HIDD + col) = make_float2(v10, v11);
            }
        }
    }
}

// ---------------- 2) deterministic counting sorts (fused, transposed layouts) ----------------
__global__ void khist2(const int* __restrict__ ei)
{
    __shared__ int cnt[NSEG];
    __shared__ int rcnt[NREL];
    const int c = blockIdx.x;
    const int t = threadIdx.x;
    for (int i = t; i < NSEG; i += 256) cnt[i] = 0;
    if (t < NREL) rcnt[t] = 0;
    __syncthreads();
    const int e = c * CHUNK + t;
    const int s = ei[e] * Nn + ei[Ee + e];
    atomicAdd(&cnt[s], 1);
    atomicAdd(&rcnt[ei[3 * Ee + e]], 1);
    __syncthreads();
    for (int i = t; i < NSEG; i += 256) g_hist[i * NCHUNK + c] = (unsigned short)cnt[i];
    if (t < NREL) g_rhist[t * NCHUNK + c] = (unsigned short)rcnt[t];
}

__global__ void kbasewarp2()
{
    const int t = threadIdx.x;
    const int s = blockIdx.x * 8 + (t >> 5);
    const int lane = t & 31;
    uint4 v4 = ((const uint4*)(g_hist + s * NCHUNK))[lane];
    int v[8] = { (int)(v4.x & 0xffff), (int)(v4.x >> 16), (int)(v4.y & 0xffff), (int)(v4.y >> 16),
                 (int)(v4.z & 0xffff), (int)(v4.z >> 16), (int)(v4.w & 0xffff), (int)(v4.w >> 16) };
    int sum = 0;
    #pragma unroll
    for (int i = 0; i < 8; i++) sum += v[i];
    int ex = sum;
    #pragma unroll
    for (int off = 1; off < 32; off <<= 1) {
        int n = __shfl_up_sync(0xffffffffu, ex, off);
        if (lane >= off) ex += n;
    }
    int run = ex - sum;
    unsigned int b[8];
    #pragma unroll
    for (int i = 0; i < 8; i++) { b[i] = (unsigned int)run; run += v[i]; }
    uint4 o;
    o.x = b[0] | (b[1] << 16); o.y = b[2] | (b[3] << 16);
    o.z = b[4] | (b[5] << 16); o.w = b[6] | (b[7] << 16);
    ((uint4*)(g_base + s * NCHUNK))[lane] = o;
    if (lane == 31) g_cnt[s] = run;
}

__global__ void kscan_all()
{
    __shared__ int wsum[32];
    __shared__ int rtot[NREL];
    const int t = threadIdx.x;   // 1024
    const int lane = t & 31, w = t >> 5;
    int a = g_cnt[2 * t], b = g_cnt[2 * t + 1];
    int s = a + b;
    int x = s;
    #pragma unroll
    for (int off = 1; off < 32; off <<= 1) {
        int n = __shfl_up_sync(0xffffffffu, x, off);
        if (lane >= off) x += n;
    }
    if (lane == 31) wsum[w] = x;
    __syncthreads();
    if (w == 0) {
        int y = wsum[lane];
        #pragma unroll
        for (int off = 1; off < 32; off <<= 1) {
            int n = __shfl_up_sync(0xffffffffu, y, off);
            if (lane >= off) y += n;
        }
        wsum[lane] = y;
    }
    __syncthreads();
    int base = (w ? wsum[w - 1] : 0) + x - s;
    g_start[2 * t + 1] = base + a;
    g_start[2 * t + 2] = base + a + b;
    if (t == 0) g_start[0] = 0;
    #pragma unroll
    for (int q = 0; q < 2; q++) {
        int r = w * 2 + q;
        uint4 v4 = ((const uint4*)(g_rhist + r * NCHUNK))[lane];
        int v[8] = { (int)(v4.x & 0xffff), (int)(v4.x >> 16), (int)(v4.y & 0xffff), (int)(v4.y >> 16),
                     (int)(v4.z & 0xffff), (int)(v4.z >> 16), (int)(v4.w & 0xffff), (int)(v4.w >> 16) };
        int sm2 = 0;
        #pragma unroll
        for (int i = 0; i < 8; i++) sm2 += v[i];
        int ex = sm2;
        #pragma unroll
        for (int off = 1; off < 32; off <<= 1) {
            int n = __shfl_up_sync(0xffffffffu, ex, off);
            if (lane >= off) ex += n;
        }
        int run = ex - sm2;
        unsigned int bb[8];
        #pragma unroll
        for (int i = 0; i < 8; i++) { bb[i] = (unsigned int)run; run += v[i]; }
        uint4 o;
        o.x = bb[0] | (bb[1] << 16); o.y = bb[2] | (bb[3] << 16);
        o.z = bb[4] | (bb[5] << 16); o.w = bb[6] | (bb[7] << 16);
        ((uint4*)(g_rbase + r * NCHUNK))[lane] = o;
        if (lane == 31) rtot[r] = run;
    }
    __syncthreads();
    if (t < 32) {
        int a2 = rtot[2 * t], b2 = rtot[2 * t + 1];
        int s2 = a2 + b2;
        int x2 = s2;
        #pragma unroll
        for (int off = 1; off < 32; off <<= 1) {
            int n = __shfl_up_sync(0xffffffffu, x2, off);
            if (t >= off) x2 += n;
        }
        int rb = x2 - s2;
        g_rstart[2 * t + 1] = rb + a2;
        g_rstart[2 * t + 2] = rb + s2;
        if (t == 0) g_rstart[0] = 0;
    }
}

__global__ void kscatter2(const int* __restrict__ ei)
{
    __shared__ int segs[CHUNK];
    __shared__ int rels[CHUNK];
    const int c = blockIdx.x;
    const int t = threadIdx.x;
    const int e = c * CHUNK + t;
    const int b = ei[e], hn = ei[Ee + e], tn = ei[2 * Ee + e], r = ei[3 * Ee + e];
    const int s = b * Nn + hn;
    segs[t] = s;
    rels[t] = r;
    __syncthreads();
    int rank = 0, rrank = 0;
    for (int i = 0; i < t; i++) {
        rank  += (segs[i] == s);
        rrank += (rels[i] == r);
    }
    int pos = g_start[s] + (int)g_base[s * NCHUNK + c] + rank;
    g_spos[e] = pos;
    g_voff[pos] = (b * Nn + tn) * HIDD;
    g_rsorted[g_rstart[r] + (int)g_rbase[r * NCHUNK + c] + rrank] = e;
}

// ---------------- 3) relation-batched logits on tensor cores (round-10 dataflow) ----------------
#define RSTR 72   // bf16 elem stride (144B rows -> conflict-free ldmatrix)
#define KSTR 68   // f32 elem stride
#define EDGE_SMEM (18432 + 18432 + 34816 + 9216 + 9216 + 192)
__global__ __launch_bounds__(256) void kedge2(const int* __restrict__ ei)
{
    extern __shared__ __align__(16) char sm[];
    __nv_bfloat16* sAh = (__nv_bfloat16*)(sm);
    __nv_bfloat16* sAl = (__nv_bfloat16*)(sm + 18432);
    float*         sK  = (float*)(sm + 36864);
    __nv_bfloat16* sRh = (__nv_bfloat16*)(sm + 71680);
    __nv_bfloat16* sRl = (__nv_bfloat16*)(sm + 80896);
    int* qoff = (int*)(sm + 90112);
    int* koff = qoff + 12;
    int* spv  = koff + 12;

    const int r  = blockIdx.x;
    const int t  = threadIdx.x;
    const int rs = g_rstart[r];
    const int total = (g_rstart[r + 1] - rs) * Hh;
    const int j0 = blockIdx.y * 128;
    if (j0 >= total) return;

    const uint32_t sAh_b = smem_u32(sAh), sAl_b = smem_u32(sAl);
    const uint32_t sRh_b = smem_u32(sRh), sRl_b = smem_u32(sRl);
    const uint32_t sK_b  = smem_u32(sK);

    // R tile loads (independent of edge offsets) — issue first
    {
        const __nv_bfloat16* Rh = g_Rhi + (r << 12);
        const __nv_bfloat16* Rl = g_Rlo + (r << 12);
        #pragma unroll
        for (int i = t; i < 512; i += 256) {
            int n = i >> 3, f = i & 7;
            uint32_t soff = (uint32_t)(n * RSTR + f * 8) * 2;
            cp16(sRh_b + soff, Rh + n * 64 + f * 8);
            cp16(sRl_b + soff, Rl + n * 64 + f * 8);
        }
        CPCOMMIT();
    }

    const int e_first = j0 / Hh;
    const int jlast = min(j0 + 127, total - 1);
    const int nloc = jlast / Hh - e_first + 1;       // <= 12

    if (t < nloc) {
        int e = g_rsorted[rs + e_first + t];
        int b = ei[e], hn = ei[Ee + e], tn = ei[2 * Ee + e];
        qoff[t] = (b * Nn + hn) * HIDD;
        koff[t] = (b * Nn + tn) * HIDD;
        spv[t]  = g_spos[e];
    }
    __syncthreads();

    // gather A (hi/lo) rows and K rows via cp.async
    #pragma unroll
    for (int i = t; i < 1024; i += 256) {
        int row = i >> 3, f = i & 7;
        int j = j0 + row; if (j > total - 1) j = total - 1;
        int le = j / Hh - e_first;
        int h = j % Hh;
        int off = qoff[le] + h * 64 + f * 8;
        uint32_t soff = (uint32_t)(row * RSTR + f * 8) * 2;
        cp16(sAh_b + soff, g_Qhi + off);
        cp16(sAl_b + soff, g_Qlo + off);
    }
    #pragma unroll
    for (int i = t; i < 2048; i += 256) {
        int row = i >> 4, f = i & 15;
        int j = j0 + row; if (j > total - 1) j = total - 1;
        int le = j / Hh - e_first;
        int h = j % Hh;
        cp16(sK_b + (uint32_t)(row * KSTR + f * 4) * 4, g_K + koff[le] + h * 64 + f * 4);
    }
    CPCOMMIT();
    CPWAIT0();
    __syncthreads();

    const int lane = t & 31;
    const int wm = t >> 5;          // warp -> rows wm*16..+15
    const int g = lane >> 3, rr = lane & 7;

    float acc[8][4];
    #pragma unroll
    for (int nt = 0; nt < 8; nt++)
        #pragma unroll
        for (int q = 0; q < 4; q++) acc[nt][q] = 0.f;

    #pragma unroll
    for (int ks = 0; ks < 4; ks++) {
        uint32_t bh[8][2], bl[8][2], af[4];
        const int bcol = ks * 16 + (g & 1) * 8;
        #pragma unroll
        for (int np = 0; np < 4; np++) {
            int brow = np * 16 + (g >> 1) * 8 + rr;
            uint32_t tmp[4];
            ldmx4(tmp, sRh_b + (uint32_t)(brow * RSTR + bcol) * 2);
            bh[2 * np][0] = tmp[0]; bh[2 * np][1] = tmp[1];
            bh[2 * np + 1][0] = tmp[2]; bh[2 * np + 1][1] = tmp[3];
            ldmx4(tmp, sRl_b + (uint32_t)(brow * RSTR + bcol) * 2);
            bl[2 * np][0] = tmp[0]; bl[2 * np][1] = tmp[1];
            bl[2 * np + 1][0] = tmp[2]; bl[2 * np + 1][1] = tmp[3];
        }
        const int acol = ks * 16 + (g >> 1) * 8;
        const int arow = wm * 16 + (g & 1) * 8 + rr;
        ldmx4(af, sAh_b + (uint32_t)(arow * RSTR + acol) * 2);
        #pragma unroll
        for (int nt = 0; nt < 8; nt++) {
            mma16816(acc[nt], af, bh[nt]);
            mma16816(acc[nt], af, bl[nt]);
        }
        ldmx4(af, sAl_b + (uint32_t)(arow * RSTR + acol) * 2);
        #pragma unroll
        for (int nt = 0; nt < 8; nt++)
            mma16816(acc[nt], af, bh[nt]);
    }

    // epilogue: dot Qp rows with K rows (fp32), write at segment-sorted position
    const int rlo = wm * 16 + (lane >> 2);
    const int rhi = rlo + 8;
    float slo = 0.f, shi = 0.f;
    #pragma unroll
    for (int nt = 0; nt < 8; nt++) {
        int col = nt * 8 + (lane & 3) * 2;
        slo += acc[nt][0] * sK[rlo * KSTR + col] + acc[nt][1] * sK[rlo * KSTR + col + 1];
        shi += acc[nt][2] * sK[rhi * KSTR + col] + acc[nt][3] * sK[rhi * KSTR + col + 1];
    }
    slo += __shfl_xor_sync(0xffffffffu, slo, 1);
    slo += __shfl_xor_sync(0xffffffffu, slo, 2);
    shi += __shfl_xor_sync(0xffffffffu, shi, 1);
    shi += __shfl_xor_sync(0xffffffffu, shi, 2);
    if ((lane & 3) == 0) {
        int j = j0 + rlo;
        if (j < total) {
            int le = j / Hh - e_first;
            g_logits[spv[le] * Hh + (j % Hh)] = slo * 0.125f;
        }
        j = j0 + rhi;
        if (j < total) {
            int le = j / Hh - e_first;
            g_logits[spv[le] * Hh + (j % Hh)] = shi * 0.125f;
        }
    }
}

// ---------------- 4) per-segment softmax + V aggregation (coalesced inputs) ----------------
__global__ __launch_bounds__(128) void kagg(float* __restrict__ out)
{
    __shared__ float    exb[CAP * Hh];   // 24 KB
    __shared__ int      voff[CAP];       // 2 KB
    __shared__ unsigned umax[Hh];
    __shared__ float    mx[Hh], dnm[Hh];

    const int s = blockIdx.x;
    const int t = threadIdx.x;
    const int beg = g_start[s];
    int cnt = g_start[s + 1] - beg;
    if (cnt > CAP) cnt = CAP;
    float* orow = out + s * HIDD;

    if (cnt == 0) {
        #pragma unroll
        for (int j = 0; j < 6; j++) orow[t + 128 * j] = 0.f;
        return;
    }

    if (t < Hh) umax[t] = 0u;
    __syncthreads();

    for (int i = t; i < cnt; i += 128) voff[i] = g_voff[beg + i];
    const float* lsrc = g_logits + (long)beg * Hh;
    for (int j = t; j < cnt * Hh; j += 128) {
        float l = lsrc[j];
        exb[j] = l;
        int h = j % Hh;
        unsigned bits = __float_as_uint(l);
        unsigned key  = (bits & 0x80000000u) ? ~bits : (bits | 0x80000000u);
        atomicMax(&umax[h], key);   // order-independent -> deterministic
    }
    __syncthreads();

    if (t < Hh) {
        unsigned key  = umax[t];
        unsigned bits = (key & 0x80000000u) ? (key & 0x7fffffffu) : ~key;
        mx[t] = __uint_as_float(bits);
    }
    __syncthreads();

    for (int j = t; j < cnt * Hh; j += 128) {
        int h = j % Hh;
        exb[j] = __expf(exb[j] - mx[h]);
    }
    __syncthreads();

    const int w = t >> 5, lane = t & 31;
    #pragma unroll
    for (int jj = 0; jj < 3; jj++) {
        int h = w * 3 + jj;
        float p = 0.f;
        for (int i = lane; i < cnt; i += 32) p += exb[i * Hh + h];
        #pragma unroll
        for (int off = 16; off; off >>= 1) p += __shfl_xor_sync(0xffffffffu, p, off);
        if (lane == 0) dnm[h] = p;
    }
    __syncthreads();

    float rd[6], accr[6];
    int hcol[6];
    #pragma unroll
    for (int j = 0; j < 6; j++) {
        int c = t + 128 * j;
        hcol[j] = c >> 6;
        rd[j] = 1.f / dnm[hcol[j]];
        accr[j] = 0.f;
    }
    #pragma unroll 2
    for (int i = 0; i < cnt; i++) {
        const float* vrow = g_V + voff[i];
        const float* exr  = &exb[i * Hh];
        #pragma unroll
        for (int j = 0; j < 6; j++) {
            float p = exr[hcol[j]] * rd[j];
            accr[j] += p * vrow[t + 128 * j];
        }
    }
    #pragma unroll
    for (int j = 0; j < 6; j++) orow[t + 128 * j] = accr[j];
}

// ---------------- launch ----------------
extern "C" void kernel_launch(void* const* d_in, const int* in_sizes, int n_in,
                              void* d_out, int out_size)
{
    const float* node_states = (const float*)d_in[0];
    const int*   edge_idx    = (const int*)  d_in[1];
    // d_in[2] = node_type_ids (unused)
    const float* Wq = (const float*)d_in[3];
    const float* bq = (const float*)d_in[4];
    const float* Wk = (const float*)d_in[5];
    const float* bk = (const float*)d_in[6];
    const float* Wv = (const float*)d_in[7];
    const float* bv = (const float*)d_in[8];
    const float* rel = (const float*)d_in[9];
    float* out = (float*)d_out;

    static cudaStream_t s1 = nullptr;
    static cudaEvent_t evRoot = nullptr, evSort = nullptr;
    static bool init_done = false;
    if (!init_done) {
        cudaFuncSetAttribute(kedge2, cudaFuncAttributeMaxDynamicSharedMemorySize, EDGE_SMEM);
        cudaFuncSetAttribute(qkv_hmma, cudaFuncAttributeMaxDynamicSharedMemorySize, QKV_SMEM);
        cudaStreamCreateWithFlags(&s1, cudaStreamNonBlocking);
        cudaEventCreateWithFlags(&evRoot, cudaEventDisableTiming);
        cudaEventCreateWithFlags(&evSort, cudaEventDisableTiming);
        init_done = true;
    }

    // ---- minimal fork: sort chain on s1, everything else on main ----
    cudaEventRecord(evRoot, 0);
    cudaStreamWaitEvent(s1, evRoot, 0);

    // s1: deterministic counting sorts (independent of conversions/GEMMs)
    khist2<<<NCHUNK, 256, 0, s1>>>(edge_idx);
    kbasewarp2<<<NSEG / 8, 256, 0, s1>>>();
    kscan_all<<<1, 1024, 0, s1>>>();
    kscatter2<<<NCHUNK, CHUNK, 0, s1>>>(edge_idx);
    cudaEventRecord(evSort, s1);

    // main: split-bf16 conversion of X, W, R^T (float4-vectorized)
    kconv<<<(CONVN + 255) / 256, 256>>>(node_states, Wq, Wk, Wv, rel);

    // main: Q,K,V projections (288 blocks -> one full concurrent wave)
    qkv_hmma<<<dim3(6, 16, 3), 256, QKV_SMEM>>>(bq, bk, bv);

    // join sort, then relation-batched logits
    cudaStreamWaitEvent(0, evSort, 0);
    kedge2<<<dim3(NREL, 120), 256, EDGE_SMEM>>>(edge_idx);

    // per-segment softmax + aggregation
    kagg<<<NSEG, 128>>>(out);
}